// round 12
// baseline (speedup 1.0000x reference)
#include <cuda_runtime.h>
#include <cstdint>

#define HW 262144
#define CHW 2621440          // 10*HW
#define MSGOFF 20971520      // 8*10*HW
#define NTILES 16384
#define NPAIRS 8192

#if defined(__CUDA_ARCH_FEAT_SM103_ALL) || defined(__CUDA_ARCH_FEAT_SM100_ALL) || \
    (defined(__CUDA_ARCH_SPECIFIC__) && (__CUDA_ARCH_SPECIFIC__ >= 1000))
#define HAS_TCGEN05 1
#else
#define HAS_TCGEN05 0
#endif

// g_fold float layout:
//  [16,6400)  tcgen05 swizzled tiles:
//    256 W1hi[32x32 SW128] (row k=20 = folded bias1) ; 1280 W1lo
//    3328 W3hi ; 4352 W3lo   (2304/2816/5376/5888 unused)
//  [6400,8536) fallback / stage-2 params:
//    +0 W1t 640 ; +640 W3t 640 ; +1280 W2f[k=32][n pad12] 384 ; +1664 W4f 384
//    +2048 B1 32 ; +2080 B3 32 ; +2112 B2 12 ; +2124 B4 12
#define FBOFF 6400
__device__ float g_fold[8544];

__device__ __forceinline__ float tf32hi(float x){
    return __uint_as_float(__float_as_uint(x) & 0xFFFFE000u);
}

// ---------------------------------------------------------------------------
// prep kernel
// ---------------------------------------------------------------------------
__global__ void fold_kernel(
    const float* __restrict__ w1,const float* __restrict__ g1,const float* __restrict__ b1,const float* __restrict__ m1,const float* __restrict__ v1,
    const float* __restrict__ w2,const float* __restrict__ g2,const float* __restrict__ b2,const float* __restrict__ m2,const float* __restrict__ v2,
    const float* __restrict__ w3,const float* __restrict__ g3,const float* __restrict__ b3,const float* __restrict__ m3,const float* __restrict__ v3,
    const float* __restrict__ w4,const float* __restrict__ g4,const float* __restrict__ b4,const float* __restrict__ m4,const float* __restrict__ v4)
{
    int tid = threadIdx.x;
    for (int i = tid; i < 1024; i += 256){       // W1 (32 rows o, 32 cols k)
        int o = i >> 5, k = i & 31;
        float s = g1[o] * rsqrtf(v1[o] + 1e-5f);
        float v = 0.f;
        if (k < 20) v = w1[o*20 + k] * s;
        else if (k == 20) v = b1[o] - m1[o]*s;
        int byo = o*128 + k*4;
        int sw = byo ^ ((byo >> 3) & 0x70);
        float h = tf32hi(v);
        g_fold[256  + (sw >> 2)] = h;
        g_fold[1280 + (sw >> 2)] = v - h;
    }
    for (int i = tid; i < 1024; i += 256){       // W3
        int o = i >> 5, k = i & 31;
        float s = g3[o] * rsqrtf(v3[o] + 1e-5f);
        float v = 0.f;
        if (k < 20) v = w3[o*20 + k] * s;
        else if (k == 20) v = b3[o] - m3[o]*s;
        int byo = o*128 + k*4;
        int sw = byo ^ ((byo >> 3) & 0x70);
        float h = tf32hi(v);
        g_fold[3328 + (sw >> 2)] = h;
        g_fold[4352 + (sw >> 2)] = v - h;
    }
    // fallback / stage-2 layouts
    for (int idx = tid; idx < 640; idx += 256){
        int c = idx >> 5, o = idx & 31;
        float s1 = g1[o] * rsqrtf(v1[o] + 1e-5f);
        g_fold[FBOFF + idx] = w1[o * 20 + c] * s1;
        float s3 = g3[o] * rsqrtf(v3[o] + 1e-5f);
        g_fold[FBOFF + 640 + idx] = w3[o * 20 + c] * s3;
    }
    for (int idx = tid; idx < 384; idx += 256){
        int o = idx / 12, c = idx % 12;          // o = hidden k, c = out channel
        float v2v = 0.f, v4v = 0.f;
        if (c < 10){
            float s2 = g2[c] * rsqrtf(v2[c] + 1e-5f); v2v = w2[c * 32 + o] * s2;
            float s4 = g4[c] * rsqrtf(v4[c] + 1e-5f); v4v = w4[c * 32 + o] * s4;
        }
        g_fold[FBOFF + 1280 + idx] = v2v;
        g_fold[FBOFF + 1664 + idx] = v4v;
    }
    if (tid < 32){
        float s1 = g1[tid] * rsqrtf(v1[tid] + 1e-5f);
        g_fold[FBOFF + 2048 + tid] = b1[tid] - m1[tid] * s1;
        float s3 = g3[tid] * rsqrtf(v3[tid] + 1e-5f);
        g_fold[FBOFF + 2080 + tid] = b3[tid] - m3[tid] * s3;
    } else if (tid < 44){
        int c = tid - 32;
        float val = 0.f;
        if (c < 10){ float s = g2[c]*rsqrtf(v2[c] + 1e-5f); val = b2[c] - m2[c]*s; }
        g_fold[FBOFF + 2112 + c] = val;
    } else if (tid < 56){
        int c = tid - 44;
        float val = 0.f;
        if (c < 10){ float s = g4[c]*rsqrtf(v4[c] + 1e-5f); val = b4[c] - m4[c]*s; }
        g_fold[FBOFF + 2124 + c] = val;
    }
}

// ---------------------------------------------------------------------------
// common helpers
// ---------------------------------------------------------------------------
__device__ __forceinline__ uint32_t s2u(const void* p){
    uint32_t a;
    asm("{ .reg .u64 t; cvta.to.shared.u64 t, %1; cvt.u32.u64 %0, t; }" : "=r"(a) : "l"(p));
    return a;
}
__device__ __forceinline__ float2 ffma2(float2 a, float2 b, float2 c) {
    float2 d;
    asm("{\n\t"
        ".reg .b64 ra, rb, rc;\n\t"
        "mov.b64 ra, {%2, %3};\n\t"
        "mov.b64 rb, {%4, %5};\n\t"
        "mov.b64 rc, {%6, %7};\n\t"
        "fma.rn.f32x2 rc, ra, rb, rc;\n\t"
        "mov.b64 {%0, %1}, rc;\n\t"
        "}"
        : "=f"(d.x), "=f"(d.y)
        : "f"(a.x), "f"(a.y), "f"(b.x), "f"(b.y), "f"(c.x), "f"(c.y));
    return d;
}

// conv2 in registers: out10 = relu(W[32x10] . h32 + b), W rows k*12 floats
__device__ __forceinline__ void conv2_reg(const float* __restrict__ h,
                                          const float* __restrict__ ws,
                                          const float* __restrict__ bs,
                                          float* __restrict__ o){
    float2 acc[5];
#pragma unroll
    for (int n = 0; n < 5; n++) acc[n] = *reinterpret_cast<const float2*>(bs + 2*n);
#pragma unroll
    for (int k = 0; k < 32; k++){
        float2 hb = make_float2(h[k], h[k]);
        const float* r = ws + k * 12;
        float4 wa = *reinterpret_cast<const float4*>(r);
        float4 wb = *reinterpret_cast<const float4*>(r + 4);
        float2 wc = *reinterpret_cast<const float2*>(r + 8);
        acc[0] = ffma2(make_float2(wa.x, wa.y), hb, acc[0]);
        acc[1] = ffma2(make_float2(wa.z, wa.w), hb, acc[1]);
        acc[2] = ffma2(make_float2(wb.x, wb.y), hb, acc[2]);
        acc[3] = ffma2(make_float2(wb.z, wb.w), hb, acc[3]);
        acc[4] = ffma2(wc, hb, acc[4]);
    }
#pragma unroll
    for (int n = 0; n < 5; n++){
        o[2*n]   = fmaxf(acc[n].x, 0.f);
        o[2*n+1] = fmaxf(acc[n].y, 0.f);
    }
}

#if HAS_TCGEN05
// ---------------------------------------------------------------------------
// tcgen05 helpers (sm_103a-only pass)
// ---------------------------------------------------------------------------
__device__ __forceinline__ uint64_t sdesc(uint32_t addr){
    // SW128, version=1 (Blackwell), SBO=64, LBO=1 (K-major, 128B rows)
    return 0x4000404000010000ULL | (uint64_t)((addr >> 4) & 0x3FFF);
}
__device__ __forceinline__ void mma_tf32(uint32_t d, uint64_t a, uint64_t b, uint32_t idesc, uint32_t en){
    asm volatile("{\n\t"
        ".reg .pred p;\n\t"
        "setp.ne.u32 p, %4, 0;\n\t"
        "tcgen05.mma.cta_group::1.kind::tf32 [%0], %1, %2, %3, {%5, %5, %5, %5}, p;\n\t"
        "}"
        :: "r"(d), "l"(a), "l"(b), "r"(idesc), "r"(en), "r"(0u) : "memory");
}
__device__ __forceinline__ void issue_stage3(uint32_t d, uint64_t ah, uint64_t al,
                                             uint64_t bh, uint64_t bl, uint32_t idesc){
    uint32_t en = 0;
#pragma unroll
    for (int k = 0; k < 3; k++){ mma_tf32(d, ah + 2*k, bh + 2*k, idesc, en); en = 1; }
#pragma unroll
    for (int k = 0; k < 3; k++)  mma_tf32(d, ah + 2*k, bl + 2*k, idesc, 1);
#pragma unroll
    for (int k = 0; k < 3; k++)  mma_tf32(d, al + 2*k, bh + 2*k, idesc, 1);
}
__device__ __forceinline__ void tc_commit(uint32_t mbar){
    asm volatile("tcgen05.commit.cta_group::1.mbarrier::arrive::one.shared::cluster.b64 [%0];"
                 :: "r"(mbar) : "memory");
}
__device__ __forceinline__ void mbar_wait(uint32_t mbar, uint32_t ph){
    asm volatile("{\n\t"
        ".reg .pred P;\n\t"
        "LW%=:\n\t"
        "mbarrier.try_wait.parity.acquire.cta.shared::cta.b64 P, [%0], %1, 0x989680;\n\t"
        "@P bra LD%=;\n\t"
        "bra LW%=;\n\t"
        "LD%=:\n\t"
        "}" :: "r"(mbar), "r"(ph) : "memory");
}
__device__ __forceinline__ void fence_proxy(){ asm volatile("fence.proxy.async.shared::cta;" ::: "memory"); }
__device__ __forceinline__ void tc_fence_after(){ asm volatile("tcgen05.fence::after_thread_sync;" ::: "memory"); }
__device__ __forceinline__ void tc_fence_before(){ asm volatile("tcgen05.fence::before_thread_sync;" ::: "memory"); }
__device__ __forceinline__ void tc_wait_ld(){ asm volatile("tcgen05.wait::ld.sync.aligned;" ::: "memory"); }
__device__ __forceinline__ void wg_bar(int id){ asm volatile("bar.sync %0, 128;" :: "r"(id) : "memory"); }

__device__ __forceinline__ void ldtm32(uint32_t a, uint32_t* r){
    asm volatile("tcgen05.ld.sync.aligned.32x32b.x32.b32 "
        "{%0,%1,%2,%3,%4,%5,%6,%7,%8,%9,%10,%11,%12,%13,%14,%15,"
        "%16,%17,%18,%19,%20,%21,%22,%23,%24,%25,%26,%27,%28,%29,%30,%31}, [%32];"
        : "=r"(r[0]),"=r"(r[1]),"=r"(r[2]),"=r"(r[3]),"=r"(r[4]),"=r"(r[5]),"=r"(r[6]),"=r"(r[7]),
          "=r"(r[8]),"=r"(r[9]),"=r"(r[10]),"=r"(r[11]),"=r"(r[12]),"=r"(r[13]),"=r"(r[14]),"=r"(r[15]),
          "=r"(r[16]),"=r"(r[17]),"=r"(r[18]),"=r"(r[19]),"=r"(r[20]),"=r"(r[21]),"=r"(r[22]),"=r"(r[23]),
          "=r"(r[24]),"=r"(r[25]),"=r"(r[26]),"=r"(r[27]),"=r"(r[28]),"=r"(r[29]),"=r"(r[30]),"=r"(r[31])
        : "r"(a));
}
__device__ __forceinline__ void sts4(uint32_t a, float x, float y, float z, float w){
    asm volatile("st.shared.v4.b32 [%0], {%1,%2,%3,%4};" :: "r"(a),"f"(x),"f"(y),"f"(z),"f"(w) : "memory");
}
// 20 data cols + constant-1 bias col (20) + zero pad (21..23)
__device__ __forceinline__ void store24(uint32_t rowh, uint32_t rowl, int sx, const float* v){
#pragma unroll
    for (int g = 0; g < 5; g++){
        uint32_t off = (uint32_t)((g ^ sx) * 16);
        float h0 = tf32hi(v[4*g]),   h1 = tf32hi(v[4*g+1]);
        float h2 = tf32hi(v[4*g+2]), h3 = tf32hi(v[4*g+3]);
        sts4(rowh + off, h0, h1, h2, h3);
        sts4(rowl + off, v[4*g]-h0, v[4*g+1]-h1, v[4*g+2]-h2, v[4*g+3]-h3);
    }
    uint32_t off = (uint32_t)((5 ^ sx) * 16);
    sts4(rowh + off, 1.f, 0.f, 0.f, 0.f);
    sts4(rowl + off, 0.f, 0.f, 0.f, 0.f);
}
#else
// ---------------------------------------------------------------------------
// fallback helper: round-2 fused block (2 pixels, ffma2)
// ---------------------------------------------------------------------------
__device__ __forceinline__ void run_block_fb(
    const float2 (&xb)[2][20],
    const float* __restrict__ sWt, const float* __restrict__ sBa,
    const float* __restrict__ sW2, const float* __restrict__ sBb,
    float2 (&out2)[5][2])
{
#pragma unroll
    for (int cp = 0; cp < 5; cp++) {
        float2 bb = *reinterpret_cast<const float2*>(sBb + 2 * cp);
        out2[cp][0] = bb; out2[cp][1] = bb;
    }
#pragma unroll
    for (int ob = 0; ob < 32; ob += 4) {
        float2 b01 = *reinterpret_cast<const float2*>(sBa + ob);
        float2 b23 = *reinterpret_cast<const float2*>(sBa + ob + 2);
        float2 a00 = b01, a01 = b01, a10 = b23, a11 = b23;
#pragma unroll
        for (int c = 0; c < 20; c++) {
            float4 w = *reinterpret_cast<const float4*>(sWt + c * 32 + ob);
            float2 w01 = make_float2(w.x, w.y);
            float2 w23 = make_float2(w.z, w.w);
            a00 = ffma2(w01, xb[0][c], a00);
            a01 = ffma2(w01, xb[1][c], a01);
            a10 = ffma2(w23, xb[0][c], a10);
            a11 = ffma2(w23, xb[1][c], a11);
        }
        a00.x = fmaxf(a00.x, 0.f); a00.y = fmaxf(a00.y, 0.f);
        a01.x = fmaxf(a01.x, 0.f); a01.y = fmaxf(a01.y, 0.f);
        a10.x = fmaxf(a10.x, 0.f); a10.y = fmaxf(a10.y, 0.f);
        a11.x = fmaxf(a11.x, 0.f); a11.y = fmaxf(a11.y, 0.f);
#pragma unroll
        for (int j = 0; j < 4; j++) {
            float h0 = (j == 0) ? a00.x : (j == 1) ? a00.y : (j == 2) ? a10.x : a10.y;
            float h1 = (j == 0) ? a01.x : (j == 1) ? a01.y : (j == 2) ? a11.x : a11.y;
            float2 hb0 = make_float2(h0, h0);
            float2 hb1 = make_float2(h1, h1);
            const float* r = sW2 + (ob + j) * 12;
            float4 wa = *reinterpret_cast<const float4*>(r);
            float4 wb = *reinterpret_cast<const float4*>(r + 4);
            float2 wc = *reinterpret_cast<const float2*>(r + 8);
            float2 w0 = make_float2(wa.x, wa.y);
            float2 w1 = make_float2(wa.z, wa.w);
            float2 w2 = make_float2(wb.x, wb.y);
            float2 w3 = make_float2(wb.z, wb.w);
            out2[0][0] = ffma2(w0, hb0, out2[0][0]); out2[0][1] = ffma2(w0, hb1, out2[0][1]);
            out2[1][0] = ffma2(w1, hb0, out2[1][0]); out2[1][1] = ffma2(w1, hb1, out2[1][1]);
            out2[2][0] = ffma2(w2, hb0, out2[2][0]); out2[2][1] = ffma2(w2, hb1, out2[2][1]);
            out2[3][0] = ffma2(w3, hb0, out2[3][0]); out2[3][1] = ffma2(w3, hb1, out2[3][1]);
            out2[4][0] = ffma2(wc, hb0, out2[4][0]); out2[4][1] = ffma2(wc, hb1, out2[4][1]);
        }
    }
#pragma unroll
    for (int cp = 0; cp < 5; cp++) {
        out2[cp][0].x = fmaxf(out2[cp][0].x, 0.f); out2[cp][0].y = fmaxf(out2[cp][0].y, 0.f);
        out2[cp][1].x = fmaxf(out2[cp][1].x, 0.f); out2[cp][1].y = fmaxf(out2[cp][1].y, 0.f);
    }
}
#endif

// ---------------------------------------------------------------------------
// fused kernel: conv1 on tcgen05 (2 tiles in flight per wg), conv2 on FMA pipe
// SMEM bytes: 0 tmem ptr; 8..56 mbar[6]; floats[256..6232) params;
//             26624 + wg*65536: per-wg A/B double buffer (4 x 16KB)
// ---------------------------------------------------------------------------
__global__ void __launch_bounds__(384, 1) fused_kernel(
    const float* __restrict__ xf, const float* __restrict__ xh1,
    const float* __restrict__ xh2, float* __restrict__ out)
{
#if HAS_TCGEN05
    extern __shared__ char smem[];
    float* sf = (float*)smem;
    uint32_t sb = s2u(smem);
    int tid = threadIdx.x;
    int wg  = tid >> 7;
    int wt  = tid & 127;

    // param copy: swizzled W1/W3 tiles + stage-2 [k][n] mats + biases
    for (int i = tid; i < 5120; i += 384) sf[256 + i] = g_fold[256 + i];
    for (int i = tid; i < 856; i += 384)  sf[5376 + i] = g_fold[FBOFF + 1280 + i];

    if (tid < 32){
        asm volatile("tcgen05.alloc.cta_group::1.sync.aligned.shared::cta.b32 [%0], %1;"
                     :: "r"(sb), "r"(256u) : "memory");
        asm volatile("tcgen05.relinquish_alloc_permit.cta_group::1.sync.aligned;" ::: "memory");
    }
    if (tid >= 32 && tid < 38){
        uint32_t mb = sb + 8 + (uint32_t)(tid - 32) * 8;
        asm volatile("mbarrier.init.shared.b64 [%0], %1;" :: "r"(mb), "r"(1u) : "memory");
    }
    fence_proxy();
    __syncthreads();
    uint32_t tmem;
    asm volatile("ld.shared.b32 %0, [%1];" : "=r"(tmem) : "r"(sb));

    const float* w2s = sf + 5376;   // [32][12]
    const float* w4s = sf + 5760;
    const float* b2s = sf + 6208;
    const float* b4s = sf + 6220;

    uint32_t mbA = sb + 8 + (uint32_t)(wg * 2) * 8;
    uint32_t mbB = mbA + 8;
    uint32_t base = sb + 26624 + (uint32_t)wg * 65536;
    uint32_t bufAh = base, bufAl = base + 16384;
    uint32_t bufBh = base + 32768, bufBl = base + 49152;
    uint64_t dAh = sdesc(bufAh), dAl = sdesc(bufAl);
    uint64_t dBh = sdesc(bufBh), dBl = sdesc(bufBl);
    uint64_t dW1h = sdesc(sb + 1024),  dW1l = sdesc(sb + 5120);
    uint64_t dW3h = sdesc(sb + 13312), dW3l = sdesc(sb + 17408);
    const uint32_t ID32 = (1u<<4) | (2u<<7) | (2u<<10) | (4u<<17) | (8u<<24);
    uint32_t tmA = tmem + (uint32_t)wg * 64;
    uint32_t tmB = tmA + 32;
    uint32_t phA = 0, phB = 0;
    int bid = wg + 1;
    uint32_t rowAh = bufAh + (uint32_t)wt * 128, rowAl = bufAl + (uint32_t)wt * 128;
    uint32_t rowBh = bufBh + (uint32_t)wt * 128, rowBl = bufBl + (uint32_t)wt * 128;
    int sx = wt & 7;

    for (int p = blockIdx.x * 3 + wg; p < NPAIRS; p += 444){
        int tA = 2 * p, tB = 2 * p + 1;
        size_t gA = (size_t)(tA >> 11) * CHW + (size_t)((tA & 2047) << 7) + (size_t)wt;
        size_t gB = (size_t)(tB >> 11) * CHW + (size_t)((tB & 2047) << 7) + (size_t)wt;

        float xA[20], fA[10], xB[20], fB[10];
#pragma unroll
        for (int c = 0; c < 10; c++) xA[c]      = xh1[gA + (size_t)c * HW];
#pragma unroll
        for (int c = 0; c < 10; c++) xA[10 + c] = xh2[gA + (size_t)c * HW];
#pragma unroll
        for (int c = 0; c < 10; c++) xB[c]      = xh1[gB + (size_t)c * HW];
#pragma unroll
        for (int c = 0; c < 10; c++) xB[10 + c] = xh2[gB + (size_t)c * HW];
#pragma unroll
        for (int c = 0; c < 10; c++) fA[c]      = xf [gA + (size_t)c * HW];
#pragma unroll
        for (int c = 0; c < 10; c++) fB[c]      = xf [gB + (size_t)c * HW];

        // ---- stage 1: both conv1 MMAs issued together ----
        store24(rowAh, rowAl, sx, xA);
        store24(rowBh, rowBl, sx, xB);
        fence_proxy();
        wg_bar(bid);
        if (wt == 0){
            tc_fence_after();
            issue_stage3(tmA, dAh, dAl, dW1h, dW1l, ID32); tc_commit(mbA);
            issue_stage3(tmB, dBh, dBl, dW1h, dW1l, ID32); tc_commit(mbB);
        }

        // ---- epi1 A: msgA, refill bufA ----
        float msgA[10], msgB[10];
        mbar_wait(mbA, phA); phA ^= 1;
        tc_fence_after();
        {
            uint32_t d[32]; ldtm32(tmA, d); tc_wait_ld(); tc_fence_before();
            float h[32];
#pragma unroll
            for (int j = 0; j < 32; j++) h[j] = fmaxf(__uint_as_float(d[j]), 0.f);
            conv2_reg(h, w2s, b2s, msgA);
        }
#pragma unroll
        for (int j = 0; j < 10; j++) out[MSGOFF + gA + (size_t)j * HW] = msgA[j];
        {
            float a2[20];
#pragma unroll
            for (int c = 0; c < 10; c++){ a2[c] = fA[c]; a2[10 + c] = msgA[c]; }
            store24(rowAh, rowAl, sx, a2);
        }

        // ---- epi1 B ----
        mbar_wait(mbB, phB); phB ^= 1;
        tc_fence_after();
        {
            uint32_t d[32]; ldtm32(tmB, d); tc_wait_ld(); tc_fence_before();
            float h[32];
#pragma unroll
            for (int j = 0; j < 32; j++) h[j] = fmaxf(__uint_as_float(d[j]), 0.f);
            conv2_reg(h, w2s, b2s, msgB);
        }
#pragma unroll
        for (int j = 0; j < 10; j++) out[MSGOFF + gB + (size_t)j * HW] = msgB[j];
        {
            float a2[20];
#pragma unroll
            for (int c = 0; c < 10; c++){ a2[c] = fB[c]; a2[10 + c] = msgB[c]; }
            store24(rowBh, rowBl, sx, a2);
        }

        // ---- stage 2: both conv1' MMAs ----
        fence_proxy();
        wg_bar(bid);
        if (wt == 0){
            tc_fence_after();
            issue_stage3(tmA, dAh, dAl, dW3h, dW3l, ID32); tc_commit(mbA);
            issue_stage3(tmB, dBh, dBl, dW3h, dW3l, ID32); tc_commit(mbB);
        }

        // ---- epi2 A ----
        mbar_wait(mbA, phA); phA ^= 1;
        tc_fence_after();
        {
            uint32_t d[32]; ldtm32(tmA, d); tc_wait_ld(); tc_fence_before();
            float h[32];
#pragma unroll
            for (int j = 0; j < 32; j++) h[j] = fmaxf(__uint_as_float(d[j]), 0.f);
            float res[10];
            conv2_reg(h, w4s, b4s, res);
#pragma unroll
            for (int j = 0; j < 10; j++) out[gA + (size_t)j * HW] = res[j];
        }

        // ---- epi2 B ----
        mbar_wait(mbB, phB); phB ^= 1;
        tc_fence_after();
        {
            uint32_t d[32]; ldtm32(tmB, d); tc_wait_ld(); tc_fence_before();
            float h[32];
#pragma unroll
            for (int j = 0; j < 32; j++) h[j] = fmaxf(__uint_as_float(d[j]), 0.f);
            float res[10];
            conv2_reg(h, w4s, b4s, res);
#pragma unroll
            for (int j = 0; j < 10; j++) out[gB + (size_t)j * HW] = res[j];
        }
    }
    __syncthreads();
    if (tid < 32){
        asm volatile("tcgen05.dealloc.cta_group::1.sync.aligned.b32 %0, %1;" :: "r"(tmem), "r"(256u));
    }
#else
    // ------------------- fallback: round-2 ffma2 path -------------------
    extern __shared__ char smem[];
    float* sf = (float*)smem;
    {
        const float4* src = reinterpret_cast<const float4*>(g_fold + FBOFF);
        float4* dst = reinterpret_cast<float4*>(sf);
        for (int i = threadIdx.x; i < 534; i += 384) dst[i] = src[i];
    }
    __syncthreads();
    const float* sW1t = sf;
    const float* sW3t = sf + 640;
    const float* sW2f = sf + 1280;
    const float* sW4f = sf + 1664;
    const float* sB1  = sf + 2048;
    const float* sB3  = sf + 2080;
    const float* sB2  = sf + 2112;
    const float* sB4  = sf + 2124;

    const int stride = gridDim.x * 384;
    for (int t = blockIdx.x * 384 + threadIdx.x; t < 1048576; t += stride){
        int b  = t >> 17;
        int hw = (t & 0x1FFFF) << 1;
        size_t base = (size_t)b * CHW + hw;
        const float* ph1 = xh1 + base;
        const float* ph2 = xh2 + base;
        const float* pf  = xf  + base;
        float* po_new = out + base;
        float* po_msg = out + (size_t)MSGOFF + base;

        float2 xb[2][20];
#pragma unroll
        for (int c = 0; c < 10; c++) {
            float2 v = *reinterpret_cast<const float2*>(ph1 + (size_t)c * HW);
            xb[0][c] = make_float2(v.x, v.x);
            xb[1][c] = make_float2(v.y, v.y);
        }
#pragma unroll
        for (int c = 0; c < 10; c++) {
            float2 v = *reinterpret_cast<const float2*>(ph2 + (size_t)c * HW);
            xb[0][10 + c] = make_float2(v.x, v.x);
            xb[1][10 + c] = make_float2(v.y, v.y);
        }

        float2 msg2[5][2];
        run_block_fb(xb, sW1t, sB1, sW2f, sB2, msg2);

#pragma unroll
        for (int cp = 0; cp < 5; cp++) {
            float2 m0 = msg2[cp][0], m1 = msg2[cp][1];
            *reinterpret_cast<float2*>(po_msg + (size_t)(2 * cp)     * HW) = make_float2(m0.x, m1.x);
            *reinterpret_cast<float2*>(po_msg + (size_t)(2 * cp + 1) * HW) = make_float2(m0.y, m1.y);
            xb[0][10 + 2 * cp]     = make_float2(m0.x, m0.x);
            xb[0][10 + 2 * cp + 1] = make_float2(m0.y, m0.y);
            xb[1][10 + 2 * cp]     = make_float2(m1.x, m1.x);
            xb[1][10 + 2 * cp + 1] = make_float2(m1.y, m1.y);
        }
#pragma unroll
        for (int c = 0; c < 10; c++) {
            float2 v = *reinterpret_cast<const float2*>(pf + (size_t)c * HW);
            xb[0][c] = make_float2(v.x, v.x);
            xb[1][c] = make_float2(v.y, v.y);
        }

        float2 r2[5][2];
        run_block_fb(xb, sW3t, sB3, sW4f, sB4, r2);

#pragma unroll
        for (int cp = 0; cp < 5; cp++) {
            float2 r0 = r2[cp][0], r1 = r2[cp][1];
            *reinterpret_cast<float2*>(po_new + (size_t)(2 * cp)     * HW) = make_float2(r0.x, r1.x);
            *reinterpret_cast<float2*>(po_new + (size_t)(2 * cp + 1) * HW) = make_float2(r0.y, r1.y);
        }
    }
#endif
}

extern "C" void kernel_launch(void* const* d_in, const int* in_sizes, int n_in,
                              void* d_out, int out_size) {
    const float* xf  = (const float*)d_in[0];
    const float* xh1 = (const float*)d_in[1];
    const float* xh2 = (const float*)d_in[2];

    fold_kernel<<<1, 256>>>(
        (const float*)d_in[3],  (const float*)d_in[4],  (const float*)d_in[5],
        (const float*)d_in[6],  (const float*)d_in[7],
        (const float*)d_in[8],  (const float*)d_in[9],  (const float*)d_in[10],
        (const float*)d_in[11], (const float*)d_in[12],
        (const float*)d_in[13], (const float*)d_in[14], (const float*)d_in[15],
        (const float*)d_in[16], (const float*)d_in[17],
        (const float*)d_in[18], (const float*)d_in[19], (const float*)d_in[20],
        (const float*)d_in[21], (const float*)d_in[22]);

    cudaFuncSetAttribute(fused_kernel, cudaFuncAttributeMaxDynamicSharedMemorySize, 223232);
    fused_kernel<<<148, 384, 223232>>>(xf, xh1, xh2, (float*)d_out);
}

// round 13
// speedup vs baseline: 1.1028x; 1.1028x over previous
#include <cuda_runtime.h>
#include <cstdint>

#define HW 262144
#define CHW 2621440          // 10*HW
#define MSGOFF 20971520      // 8*10*HW
#define NTILES 16384

#if defined(__CUDA_ARCH_FEAT_SM103_ALL) || defined(__CUDA_ARCH_FEAT_SM100_ALL) || \
    (defined(__CUDA_ARCH_SPECIFIC__) && (__CUDA_ARCH_SPECIFIC__ >= 1000))
#define HAS_TCGEN05 1
#else
#define HAS_TCGEN05 0
#endif

// g_fold float layout:
//  [16,6400)  tcgen05 swizzled tiles:
//    256 W1hi[32x32 SW128] (row k=20 = folded bias1) ; 1280 W1lo
//    3328 W3hi ; 4352 W3lo
//  [6400,8536) fallback / stage-2 params:
//    +0 W1t 640 ; +640 W3t 640 ; +1280 W2f[k=32][n pad12] 384 ; +1664 W4f 384
//    +2048 B1 32 ; +2080 B3 32 ; +2112 B2 12 ; +2124 B4 12
#define FBOFF 6400
__device__ float g_fold[8544];

__device__ __forceinline__ float tf32hi(float x){
    return __uint_as_float(__float_as_uint(x) & 0xFFFFE000u);
}

// ---------------------------------------------------------------------------
// prep kernel
// ---------------------------------------------------------------------------
__global__ void fold_kernel(
    const float* __restrict__ w1,const float* __restrict__ g1,const float* __restrict__ b1,const float* __restrict__ m1,const float* __restrict__ v1,
    const float* __restrict__ w2,const float* __restrict__ g2,const float* __restrict__ b2,const float* __restrict__ m2,const float* __restrict__ v2,
    const float* __restrict__ w3,const float* __restrict__ g3,const float* __restrict__ b3,const float* __restrict__ m3,const float* __restrict__ v3,
    const float* __restrict__ w4,const float* __restrict__ g4,const float* __restrict__ b4,const float* __restrict__ m4,const float* __restrict__ v4)
{
    int tid = threadIdx.x;
    for (int i = tid; i < 1024; i += 256){       // W1 (32 rows o, 32 cols k)
        int o = i >> 5, k = i & 31;
        float s = g1[o] * rsqrtf(v1[o] + 1e-5f);
        float v = 0.f;
        if (k < 20) v = w1[o*20 + k] * s;
        else if (k == 20) v = b1[o] - m1[o]*s;
        int byo = o*128 + k*4;
        int sw = byo ^ ((byo >> 3) & 0x70);
        float h = tf32hi(v);
        g_fold[256  + (sw >> 2)] = h;
        g_fold[1280 + (sw >> 2)] = v - h;
    }
    for (int i = tid; i < 1024; i += 256){       // W3
        int o = i >> 5, k = i & 31;
        float s = g3[o] * rsqrtf(v3[o] + 1e-5f);
        float v = 0.f;
        if (k < 20) v = w3[o*20 + k] * s;
        else if (k == 20) v = b3[o] - m3[o]*s;
        int byo = o*128 + k*4;
        int sw = byo ^ ((byo >> 3) & 0x70);
        float h = tf32hi(v);
        g_fold[3328 + (sw >> 2)] = h;
        g_fold[4352 + (sw >> 2)] = v - h;
    }
    // fallback / stage-2 layouts
    for (int idx = tid; idx < 640; idx += 256){
        int c = idx >> 5, o = idx & 31;
        float s1 = g1[o] * rsqrtf(v1[o] + 1e-5f);
        g_fold[FBOFF + idx] = w1[o * 20 + c] * s1;
        float s3 = g3[o] * rsqrtf(v3[o] + 1e-5f);
        g_fold[FBOFF + 640 + idx] = w3[o * 20 + c] * s3;
    }
    for (int idx = tid; idx < 384; idx += 256){
        int o = idx / 12, c = idx % 12;          // o = hidden k, c = out channel
        float v2v = 0.f, v4v = 0.f;
        if (c < 10){
            float s2 = g2[c] * rsqrtf(v2[c] + 1e-5f); v2v = w2[c * 32 + o] * s2;
            float s4 = g4[c] * rsqrtf(v4[c] + 1e-5f); v4v = w4[c * 32 + o] * s4;
        }
        g_fold[FBOFF + 1280 + idx] = v2v;
        g_fold[FBOFF + 1664 + idx] = v4v;
    }
    if (tid < 32){
        float s1 = g1[tid] * rsqrtf(v1[tid] + 1e-5f);
        g_fold[FBOFF + 2048 + tid] = b1[tid] - m1[tid] * s1;
        float s3 = g3[tid] * rsqrtf(v3[tid] + 1e-5f);
        g_fold[FBOFF + 2080 + tid] = b3[tid] - m3[tid] * s3;
    } else if (tid < 44){
        int c = tid - 32;
        float val = 0.f;
        if (c < 10){ float s = g2[c]*rsqrtf(v2[c] + 1e-5f); val = b2[c] - m2[c]*s; }
        g_fold[FBOFF + 2112 + c] = val;
    } else if (tid < 56){
        int c = tid - 44;
        float val = 0.f;
        if (c < 10){ float s = g4[c]*rsqrtf(v4[c] + 1e-5f); val = b4[c] - m4[c]*s; }
        g_fold[FBOFF + 2124 + c] = val;
    }
}

// ---------------------------------------------------------------------------
// common helpers
// ---------------------------------------------------------------------------
__device__ __forceinline__ uint32_t s2u(const void* p){
    uint32_t a;
    asm("{ .reg .u64 t; cvta.to.shared.u64 t, %1; cvt.u32.u64 %0, t; }" : "=r"(a) : "l"(p));
    return a;
}
__device__ __forceinline__ float2 ffma2(float2 a, float2 b, float2 c) {
    float2 d;
    asm("{\n\t"
        ".reg .b64 ra, rb, rc;\n\t"
        "mov.b64 ra, {%2, %3};\n\t"
        "mov.b64 rb, {%4, %5};\n\t"
        "mov.b64 rc, {%6, %7};\n\t"
        "fma.rn.f32x2 rc, ra, rb, rc;\n\t"
        "mov.b64 {%0, %1}, rc;\n\t"
        "}"
        : "=f"(d.x), "=f"(d.y)
        : "f"(a.x), "f"(a.y), "f"(b.x), "f"(b.y), "f"(c.x), "f"(c.y));
    return d;
}

// conv2 in registers: out10 = relu(W[32x10] . h32 + b), W rows k*12 floats
__device__ __forceinline__ void conv2_reg(const float* __restrict__ h,
                                          const float* __restrict__ ws,
                                          const float* __restrict__ bs,
                                          float* __restrict__ o){
    float2 acc[5];
#pragma unroll
    for (int n = 0; n < 5; n++) acc[n] = *reinterpret_cast<const float2*>(bs + 2*n);
#pragma unroll
    for (int k = 0; k < 32; k++){
        float2 hb = make_float2(h[k], h[k]);
        const float* r = ws + k * 12;
        float4 wa = *reinterpret_cast<const float4*>(r);
        float4 wb = *reinterpret_cast<const float4*>(r + 4);
        float2 wc = *reinterpret_cast<const float2*>(r + 8);
        acc[0] = ffma2(make_float2(wa.x, wa.y), hb, acc[0]);
        acc[1] = ffma2(make_float2(wa.z, wa.w), hb, acc[1]);
        acc[2] = ffma2(make_float2(wb.x, wb.y), hb, acc[2]);
        acc[3] = ffma2(make_float2(wb.z, wb.w), hb, acc[3]);
        acc[4] = ffma2(wc, hb, acc[4]);
    }
#pragma unroll
    for (int n = 0; n < 5; n++){
        o[2*n]   = fmaxf(acc[n].x, 0.f);
        o[2*n+1] = fmaxf(acc[n].y, 0.f);
    }
}

#if HAS_TCGEN05
// ---------------------------------------------------------------------------
// tcgen05 helpers (sm_103a-only pass)
// ---------------------------------------------------------------------------
__device__ __forceinline__ uint64_t sdesc(uint32_t addr){
    // SW128, version=1 (Blackwell), SBO=64, LBO=1 (K-major, 128B rows)
    return 0x4000404000010000ULL | (uint64_t)((addr >> 4) & 0x3FFF);
}
__device__ __forceinline__ void mma_tf32(uint32_t d, uint64_t a, uint64_t b, uint32_t idesc, uint32_t en){
    asm volatile("{\n\t"
        ".reg .pred p;\n\t"
        "setp.ne.u32 p, %4, 0;\n\t"
        "tcgen05.mma.cta_group::1.kind::tf32 [%0], %1, %2, %3, {%5, %5, %5, %5}, p;\n\t"
        "}"
        :: "r"(d), "l"(a), "l"(b), "r"(idesc), "r"(en), "r"(0u) : "memory");
}
__device__ __forceinline__ void issue_stage3(uint32_t d, uint64_t ah, uint64_t al,
                                             uint64_t bh, uint64_t bl, uint32_t idesc){
    uint32_t en = 0;
#pragma unroll
    for (int k = 0; k < 3; k++){ mma_tf32(d, ah + 2*k, bh + 2*k, idesc, en); en = 1; }
#pragma unroll
    for (int k = 0; k < 3; k++)  mma_tf32(d, ah + 2*k, bl + 2*k, idesc, 1);
#pragma unroll
    for (int k = 0; k < 3; k++)  mma_tf32(d, al + 2*k, bh + 2*k, idesc, 1);
}
__device__ __forceinline__ void tc_commit(uint32_t mbar){
    asm volatile("tcgen05.commit.cta_group::1.mbarrier::arrive::one.shared::cluster.b64 [%0];"
                 :: "r"(mbar) : "memory");
}
__device__ __forceinline__ void mbar_wait(uint32_t mbar, uint32_t ph){
    asm volatile("{\n\t"
        ".reg .pred P;\n\t"
        "LW%=:\n\t"
        "mbarrier.try_wait.parity.acquire.cta.shared::cta.b64 P, [%0], %1, 0x989680;\n\t"
        "@P bra LD%=;\n\t"
        "bra LW%=;\n\t"
        "LD%=:\n\t"
        "}" :: "r"(mbar), "r"(ph) : "memory");
}
__device__ __forceinline__ void fence_proxy(){ asm volatile("fence.proxy.async.shared::cta;" ::: "memory"); }
__device__ __forceinline__ void tc_fence_after(){ asm volatile("tcgen05.fence::after_thread_sync;" ::: "memory"); }
__device__ __forceinline__ void tc_fence_before(){ asm volatile("tcgen05.fence::before_thread_sync;" ::: "memory"); }
__device__ __forceinline__ void tc_wait_ld(){ asm volatile("tcgen05.wait::ld.sync.aligned;" ::: "memory"); }
__device__ __forceinline__ void wg_bar(int id){ asm volatile("bar.sync %0, 128;" :: "r"(id) : "memory"); }

__device__ __forceinline__ void ldtm32(uint32_t a, uint32_t* r){
    asm volatile("tcgen05.ld.sync.aligned.32x32b.x32.b32 "
        "{%0,%1,%2,%3,%4,%5,%6,%7,%8,%9,%10,%11,%12,%13,%14,%15,"
        "%16,%17,%18,%19,%20,%21,%22,%23,%24,%25,%26,%27,%28,%29,%30,%31}, [%32];"
        : "=r"(r[0]),"=r"(r[1]),"=r"(r[2]),"=r"(r[3]),"=r"(r[4]),"=r"(r[5]),"=r"(r[6]),"=r"(r[7]),
          "=r"(r[8]),"=r"(r[9]),"=r"(r[10]),"=r"(r[11]),"=r"(r[12]),"=r"(r[13]),"=r"(r[14]),"=r"(r[15]),
          "=r"(r[16]),"=r"(r[17]),"=r"(r[18]),"=r"(r[19]),"=r"(r[20]),"=r"(r[21]),"=r"(r[22]),"=r"(r[23]),
          "=r"(r[24]),"=r"(r[25]),"=r"(r[26]),"=r"(r[27]),"=r"(r[28]),"=r"(r[29]),"=r"(r[30]),"=r"(r[31])
        : "r"(a));
}
__device__ __forceinline__ void sts4(uint32_t a, float x, float y, float z, float w){
    asm volatile("st.shared.v4.b32 [%0], {%1,%2,%3,%4};" :: "r"(a),"f"(x),"f"(y),"f"(z),"f"(w) : "memory");
}
// 20 data cols + constant-1 bias col (20) + zero pad (21..23)
__device__ __forceinline__ void store24(uint32_t rowh, uint32_t rowl, int sx, const float* v){
#pragma unroll
    for (int g = 0; g < 5; g++){
        uint32_t off = (uint32_t)((g ^ sx) * 16);
        float h0 = tf32hi(v[4*g]),   h1 = tf32hi(v[4*g+1]);
        float h2 = tf32hi(v[4*g+2]), h3 = tf32hi(v[4*g+3]);
        sts4(rowh + off, h0, h1, h2, h3);
        sts4(rowl + off, v[4*g]-h0, v[4*g+1]-h1, v[4*g+2]-h2, v[4*g+3]-h3);
    }
    uint32_t off = (uint32_t)((5 ^ sx) * 16);
    sts4(rowh + off, 1.f, 0.f, 0.f, 0.f);
    sts4(rowl + off, 0.f, 0.f, 0.f, 0.f);
}
#else
// ---------------------------------------------------------------------------
// fallback helper: round-2 fused block (2 pixels, ffma2)
// ---------------------------------------------------------------------------
__device__ __forceinline__ void run_block_fb(
    const float2 (&xb)[2][20],
    const float* __restrict__ sWt, const float* __restrict__ sBa,
    const float* __restrict__ sW2, const float* __restrict__ sBb,
    float2 (&out2)[5][2])
{
#pragma unroll
    for (int cp = 0; cp < 5; cp++) {
        float2 bb = *reinterpret_cast<const float2*>(sBb + 2 * cp);
        out2[cp][0] = bb; out2[cp][1] = bb;
    }
#pragma unroll
    for (int ob = 0; ob < 32; ob += 4) {
        float2 b01 = *reinterpret_cast<const float2*>(sBa + ob);
        float2 b23 = *reinterpret_cast<const float2*>(sBa + ob + 2);
        float2 a00 = b01, a01 = b01, a10 = b23, a11 = b23;
#pragma unroll
        for (int c = 0; c < 20; c++) {
            float4 w = *reinterpret_cast<const float4*>(sWt + c * 32 + ob);
            float2 w01 = make_float2(w.x, w.y);
            float2 w23 = make_float2(w.z, w.w);
            a00 = ffma2(w01, xb[0][c], a00);
            a01 = ffma2(w01, xb[1][c], a01);
            a10 = ffma2(w23, xb[0][c], a10);
            a11 = ffma2(w23, xb[1][c], a11);
        }
        a00.x = fmaxf(a00.x, 0.f); a00.y = fmaxf(a00.y, 0.f);
        a01.x = fmaxf(a01.x, 0.f); a01.y = fmaxf(a01.y, 0.f);
        a10.x = fmaxf(a10.x, 0.f); a10.y = fmaxf(a10.y, 0.f);
        a11.x = fmaxf(a11.x, 0.f); a11.y = fmaxf(a11.y, 0.f);
#pragma unroll
        for (int j = 0; j < 4; j++) {
            float h0 = (j == 0) ? a00.x : (j == 1) ? a00.y : (j == 2) ? a10.x : a10.y;
            float h1 = (j == 0) ? a01.x : (j == 1) ? a01.y : (j == 2) ? a11.x : a11.y;
            float2 hb0 = make_float2(h0, h0);
            float2 hb1 = make_float2(h1, h1);
            const float* r = sW2 + (ob + j) * 12;
            float4 wa = *reinterpret_cast<const float4*>(r);
            float4 wb = *reinterpret_cast<const float4*>(r + 4);
            float2 wc = *reinterpret_cast<const float2*>(r + 8);
            float2 w0 = make_float2(wa.x, wa.y);
            float2 w1 = make_float2(wa.z, wa.w);
            float2 w2 = make_float2(wb.x, wb.y);
            float2 w3 = make_float2(wb.z, wb.w);
            out2[0][0] = ffma2(w0, hb0, out2[0][0]); out2[0][1] = ffma2(w0, hb1, out2[0][1]);
            out2[1][0] = ffma2(w1, hb0, out2[1][0]); out2[1][1] = ffma2(w1, hb1, out2[1][1]);
            out2[2][0] = ffma2(w2, hb0, out2[2][0]); out2[2][1] = ffma2(w2, hb1, out2[2][1]);
            out2[3][0] = ffma2(w3, hb0, out2[3][0]); out2[3][1] = ffma2(w3, hb1, out2[3][1]);
            out2[4][0] = ffma2(wc, hb0, out2[4][0]); out2[4][1] = ffma2(wc, hb1, out2[4][1]);
        }
    }
#pragma unroll
    for (int cp = 0; cp < 5; cp++) {
        out2[cp][0].x = fmaxf(out2[cp][0].x, 0.f); out2[cp][0].y = fmaxf(out2[cp][0].y, 0.f);
        out2[cp][1].x = fmaxf(out2[cp][1].x, 0.f); out2[cp][1].y = fmaxf(out2[cp][1].y, 0.f);
    }
}
#endif

// ---------------------------------------------------------------------------
// fused kernel: software-pipelined. Per wg: buffers X,S (32KB each), tmem tm1,tm2.
// Every mbar wait targets an MMA issued one full iteration earlier.
// SMEM: 0 tmem ptr; 8..56 mbar[6]; floats[256..6232) params;
//       26624 + wg*65536: X (hi16K+lo16K), S (hi16K+lo16K)
// ---------------------------------------------------------------------------
__global__ void __launch_bounds__(384, 1) fused_kernel(
    const float* __restrict__ xf, const float* __restrict__ xh1,
    const float* __restrict__ xh2, float* __restrict__ out)
{
#if HAS_TCGEN05
    extern __shared__ char smem[];
    float* sf = (float*)smem;
    uint32_t sb = s2u(smem);
    int tid = threadIdx.x;
    int wg  = tid >> 7;
    int wt  = tid & 127;

    for (int i = tid; i < 5120; i += 384) sf[256 + i] = g_fold[256 + i];
    for (int i = tid; i < 856; i += 384)  sf[5376 + i] = g_fold[FBOFF + 1280 + i];

    if (tid < 32){
        asm volatile("tcgen05.alloc.cta_group::1.sync.aligned.shared::cta.b32 [%0], %1;"
                     :: "r"(sb), "r"(256u) : "memory");
        asm volatile("tcgen05.relinquish_alloc_permit.cta_group::1.sync.aligned;" ::: "memory");
    }
    if (tid >= 32 && tid < 38){
        uint32_t mb = sb + 8 + (uint32_t)(tid - 32) * 8;
        asm volatile("mbarrier.init.shared.b64 [%0], %1;" :: "r"(mb), "r"(1u) : "memory");
    }
    fence_proxy();
    __syncthreads();
    uint32_t tmem;
    asm volatile("ld.shared.b32 %0, [%1];" : "=r"(tmem) : "r"(sb));

    const float* w2s = sf + 5376;   // [32][12]
    const float* w4s = sf + 5760;
    const float* b2s = sf + 6208;
    const float* b4s = sf + 6220;

    uint32_t mb1 = sb + 8 + (uint32_t)(wg * 2) * 8;
    uint32_t mb2 = mb1 + 8;
    uint32_t base = sb + 26624 + (uint32_t)wg * 65536;
    uint32_t bufXh = base,        bufXl = base + 16384;
    uint32_t bufSh = base + 32768, bufSl = base + 49152;
    uint64_t dXh = sdesc(bufXh), dXl = sdesc(bufXl);
    uint64_t dSh = sdesc(bufSh), dSl = sdesc(bufSl);
    uint64_t dW1h = sdesc(sb + 1024),  dW1l = sdesc(sb + 5120);
    uint64_t dW3h = sdesc(sb + 13312), dW3l = sdesc(sb + 17408);
    const uint32_t ID32 = (1u<<4) | (2u<<7) | (2u<<10) | (4u<<17) | (8u<<24);
    uint32_t tm1 = tmem + (uint32_t)wg * 64;
    uint32_t tm2 = tm1 + 32;
    uint32_t ph1 = 0, ph2 = 0;
    int bid = wg + 1;
    uint32_t rowXh = bufXh + (uint32_t)wt * 128, rowXl = bufXl + (uint32_t)wt * 128;
    uint32_t rowSh = bufSh + (uint32_t)wt * 128, rowSl = bufSl + (uint32_t)wt * 128;
    int sx = wt & 7;
    const int STRIDE = 444;   // 148 blocks * 3 wg

    int t0 = blockIdx.x * 3 + wg;     // always < NTILES (444 <= 16384)
    size_t g = (size_t)(t0 >> 11) * CHW + (size_t)((t0 & 2047) << 7) + (size_t)wt;

    // prologue: load x(t0), kick MMA1(t0)
    float fa[10];
    {
        float a[20];
#pragma unroll
        for (int c = 0; c < 10; c++) a[c]      = xh1[g + (size_t)c * HW];
#pragma unroll
        for (int c = 0; c < 10; c++) a[10 + c] = xh2[g + (size_t)c * HW];
#pragma unroll
        for (int c = 0; c < 10; c++) fa[c]     = xf [g + (size_t)c * HW];
        store24(rowXh, rowXl, sx, a);
        fence_proxy();
        wg_bar(bid);
        if (wt == 0){ tc_fence_after(); issue_stage3(tm1, dXh, dXl, dW1h, dW1l, ID32); tc_commit(mb1); }
    }

    size_t gPrev = 0;
    bool havePrev = false;

    for (int t = t0; t < NTILES; t += STRIDE){
        int tn = t + STRIDE;
        bool hasNext = tn < NTILES;
        int tl = hasNext ? tn : t;
        size_t gn = (size_t)(tl >> 11) * CHW + (size_t)((tl & 2047) << 7) + (size_t)wt;

        // prefetch next tile inputs (overlaps MMA1(t) completion)
        float xn[20], fn[10];
#pragma unroll
        for (int c = 0; c < 10; c++) xn[c]      = xh1[gn + (size_t)c * HW];
#pragma unroll
        for (int c = 0; c < 10; c++) xn[10 + c] = xh2[gn + (size_t)c * HW];
#pragma unroll
        for (int c = 0; c < 10; c++) fn[c]      = xf [gn + (size_t)c * HW];

        // epi1(t): mma1(t) was issued one iteration (or prologue) ago
        mbar_wait(mb1, ph1); ph1 ^= 1;
        tc_fence_after();
        float msg[10];
        {
            uint32_t d[32]; ldtm32(tm1, d); tc_wait_ld(); tc_fence_before();
            float h[32];
#pragma unroll
            for (int j = 0; j < 32; j++) h[j] = fmaxf(__uint_as_float(d[j]), 0.f);
            conv2_reg(h, w2s, b2s, msg);
        }
#pragma unroll
        for (int j = 0; j < 10; j++) out[MSGOFF + g + (size_t)j * HW] = msg[j];

        // epi2(t-1): mma2(t-1) issued one iteration ago -> near-zero wait
        if (havePrev){
            mbar_wait(mb2, ph2); ph2 ^= 1;
            tc_fence_after();
            uint32_t d[32]; ldtm32(tm2, d); tc_wait_ld(); tc_fence_before();
            float h[32];
#pragma unroll
            for (int j = 0; j < 32; j++) h[j] = fmaxf(__uint_as_float(d[j]), 0.f);
            float res[10];
            conv2_reg(h, w4s, b4s, res);
#pragma unroll
            for (int j = 0; j < 10; j++) out[gPrev + (size_t)j * HW] = res[j];
        }

        // refill buffers: S=(xf,msg)(t) safe after mb2 wait; X=x(t+1) safe after mb1 wait
        {
            float a2[20];
#pragma unroll
            for (int c = 0; c < 10; c++){ a2[c] = fa[c]; a2[10 + c] = msg[c]; }
            store24(rowSh, rowSl, sx, a2);
        }
        store24(rowXh, rowXl, sx, xn);
        fence_proxy();
        wg_bar(bid);
        if (wt == 0){
            tc_fence_after();
            issue_stage3(tm2, dSh, dSl, dW3h, dW3l, ID32); tc_commit(mb2);
            if (hasNext){ issue_stage3(tm1, dXh, dXl, dW1h, dW1l, ID32); tc_commit(mb1); }
        }

        gPrev = g; havePrev = true;
        g = gn;
#pragma unroll
        for (int c = 0; c < 10; c++) fa[c] = fn[c];
    }

    // epilogue: last tile's stage 2
    {
        mbar_wait(mb2, ph2);
        tc_fence_after();
        uint32_t d[32]; ldtm32(tm2, d); tc_wait_ld(); tc_fence_before();
        float h[32];
#pragma unroll
        for (int j = 0; j < 32; j++) h[j] = fmaxf(__uint_as_float(d[j]), 0.f);
        float res[10];
        conv2_reg(h, w4s, b4s, res);
#pragma unroll
        for (int j = 0; j < 10; j++) out[gPrev + (size_t)j * HW] = res[j];
    }

    __syncthreads();
    if (tid < 32){
        asm volatile("tcgen05.dealloc.cta_group::1.sync.aligned.b32 %0, %1;" :: "r"(tmem), "r"(256u));
    }
#else
    // ------------------- fallback: round-2 ffma2 path -------------------
    extern __shared__ char smem[];
    float* sf = (float*)smem;
    {
        const float4* src = reinterpret_cast<const float4*>(g_fold + FBOFF);
        float4* dst = reinterpret_cast<float4*>(sf);
        for (int i = threadIdx.x; i < 534; i += 384) dst[i] = src[i];
    }
    __syncthreads();
    const float* sW1t = sf;
    const float* sW3t = sf + 640;
    const float* sW2f = sf + 1280;
    const float* sW4f = sf + 1664;
    const float* sB1  = sf + 2048;
    const float* sB3  = sf + 2080;
    const float* sB2  = sf + 2112;
    const float* sB4  = sf + 2124;

    const int stride = gridDim.x * 384;
    for (int t = blockIdx.x * 384 + threadIdx.x; t < 1048576; t += stride){
        int b  = t >> 17;
        int hw = (t & 0x1FFFF) << 1;
        size_t base = (size_t)b * CHW + hw;
        const float* ph1 = xh1 + base;
        const float* ph2 = xh2 + base;
        const float* pf  = xf  + base;
        float* po_new = out + base;
        float* po_msg = out + (size_t)MSGOFF + base;

        float2 xb[2][20];
#pragma unroll
        for (int c = 0; c < 10; c++) {
            float2 v = *reinterpret_cast<const float2*>(ph1 + (size_t)c * HW);
            xb[0][c] = make_float2(v.x, v.x);
            xb[1][c] = make_float2(v.y, v.y);
        }
#pragma unroll
        for (int c = 0; c < 10; c++) {
            float2 v = *reinterpret_cast<const float2*>(ph2 + (size_t)c * HW);
            xb[0][10 + c] = make_float2(v.x, v.x);
            xb[1][10 + c] = make_float2(v.y, v.y);
        }

        float2 msg2[5][2];
        run_block_fb(xb, sW1t, sB1, sW2f, sB2, msg2);

#pragma unroll
        for (int cp = 0; cp < 5; cp++) {
            float2 m0 = msg2[cp][0], m1 = msg2[cp][1];
            *reinterpret_cast<float2*>(po_msg + (size_t)(2 * cp)     * HW) = make_float2(m0.x, m1.x);
            *reinterpret_cast<float2*>(po_msg + (size_t)(2 * cp + 1) * HW) = make_float2(m0.y, m1.y);
            xb[0][10 + 2 * cp]     = make_float2(m0.x, m0.x);
            xb[0][10 + 2 * cp + 1] = make_float2(m0.y, m0.y);
            xb[1][10 + 2 * cp]     = make_float2(m1.x, m1.x);
            xb[1][10 + 2 * cp + 1] = make_float2(m1.y, m1.y);
        }
#pragma unroll
        for (int c = 0; c < 10; c++) {
            float2 v = *reinterpret_cast<const float2*>(pf + (size_t)c * HW);
            xb[0][c] = make_float2(v.x, v.x);
            xb[1][c] = make_float2(v.y, v.y);
        }

        float2 r2[5][2];
        run_block_fb(xb, sW3t, sB3, sW4f, sB4, r2);

#pragma unroll
        for (int cp = 0; cp < 5; cp++) {
            float2 r0 = r2[cp][0], r1 = r2[cp][1];
            *reinterpret_cast<float2*>(po_new + (size_t)(2 * cp)     * HW) = make_float2(r0.x, r1.x);
            *reinterpret_cast<float2*>(po_new + (size_t)(2 * cp + 1) * HW) = make_float2(r0.y, r1.y);
        }
    }
#endif
}

extern "C" void kernel_launch(void* const* d_in, const int* in_sizes, int n_in,
                              void* d_out, int out_size) {
    const float* xf  = (const float*)d_in[0];
    const float* xh1 = (const float*)d_in[1];
    const float* xh2 = (const float*)d_in[2];

    fold_kernel<<<1, 256>>>(
        (const float*)d_in[3],  (const float*)d_in[4],  (const float*)d_in[5],
        (const float*)d_in[6],  (const float*)d_in[7],
        (const float*)d_in[8],  (const float*)d_in[9],  (const float*)d_in[10],
        (const float*)d_in[11], (const float*)d_in[12],
        (const float*)d_in[13], (const float*)d_in[14], (const float*)d_in[15],
        (const float*)d_in[16], (const float*)d_in[17],
        (const float*)d_in[18], (const float*)d_in[19], (const float*)d_in[20],
        (const float*)d_in[21], (const float*)d_in[22]);

    cudaFuncSetAttribute(fused_kernel, cudaFuncAttributeMaxDynamicSharedMemorySize, 223232);
    fused_kernel<<<148, 384, 223232>>>(xf, xh1, xh2, (float*)d_out);
}

// round 14
// speedup vs baseline: 1.2614x; 1.1438x over previous
#include <cuda_runtime.h>
#include <cstdint>

#define HW 262144
#define CHW 2621440          // 10*HW
#define MSGOFF 20971520      // 8*10*HW
#define NSUP 8192            // 256-pixel supertiles

#if defined(__CUDA_ARCH_FEAT_SM103_ALL) || defined(__CUDA_ARCH_FEAT_SM100_ALL) || \
    (defined(__CUDA_ARCH_SPECIFIC__) && (__CUDA_ARCH_SPECIFIC__ >= 1000))
#define HAS_TCGEN05 1
#else
#define HAS_TCGEN05 0
#endif

// g_fold float layout:
//  [16,6400)  tcgen05 swizzled tiles:
//    256 W1hi[32x32 SW128] (row k=20 = folded bias1) ; 1280 W1lo
//    3328 W3hi ; 4352 W3lo
//  [6400,8536) fallback / stage-2 params:
//    +0 W1t 640 ; +640 W3t 640 ; +1280 W2f[k=32][n pad12] 384 ; +1664 W4f 384
//    +2048 B1 32 ; +2080 B3 32 ; +2112 B2 12 ; +2124 B4 12
#define FBOFF 6400
__device__ float g_fold[8544];

__device__ __forceinline__ float tf32hi(float x){
    return __uint_as_float(__float_as_uint(x) & 0xFFFFE000u);
}

// ---------------------------------------------------------------------------
// prep kernel
// ---------------------------------------------------------------------------
__global__ void fold_kernel(
    const float* __restrict__ w1,const float* __restrict__ g1,const float* __restrict__ b1,const float* __restrict__ m1,const float* __restrict__ v1,
    const float* __restrict__ w2,const float* __restrict__ g2,const float* __restrict__ b2,const float* __restrict__ m2,const float* __restrict__ v2,
    const float* __restrict__ w3,const float* __restrict__ g3,const float* __restrict__ b3,const float* __restrict__ m3,const float* __restrict__ v3,
    const float* __restrict__ w4,const float* __restrict__ g4,const float* __restrict__ b4,const float* __restrict__ m4,const float* __restrict__ v4)
{
    int tid = threadIdx.x;
    for (int i = tid; i < 1024; i += 256){       // W1 (32 rows o, 32 cols k)
        int o = i >> 5, k = i & 31;
        float s = g1[o] * rsqrtf(v1[o] + 1e-5f);
        float v = 0.f;
        if (k < 20) v = w1[o*20 + k] * s;
        else if (k == 20) v = b1[o] - m1[o]*s;
        int byo = o*128 + k*4;
        int sw = byo ^ ((byo >> 3) & 0x70);
        float h = tf32hi(v);
        g_fold[256  + (sw >> 2)] = h;
        g_fold[1280 + (sw >> 2)] = v - h;
    }
    for (int i = tid; i < 1024; i += 256){       // W3
        int o = i >> 5, k = i & 31;
        float s = g3[o] * rsqrtf(v3[o] + 1e-5f);
        float v = 0.f;
        if (k < 20) v = w3[o*20 + k] * s;
        else if (k == 20) v = b3[o] - m3[o]*s;
        int byo = o*128 + k*4;
        int sw = byo ^ ((byo >> 3) & 0x70);
        float h = tf32hi(v);
        g_fold[3328 + (sw >> 2)] = h;
        g_fold[4352 + (sw >> 2)] = v - h;
    }
    // fallback / stage-2 layouts
    for (int idx = tid; idx < 640; idx += 256){
        int c = idx >> 5, o = idx & 31;
        float s1 = g1[o] * rsqrtf(v1[o] + 1e-5f);
        g_fold[FBOFF + idx] = w1[o * 20 + c] * s1;
        float s3 = g3[o] * rsqrtf(v3[o] + 1e-5f);
        g_fold[FBOFF + 640 + idx] = w3[o * 20 + c] * s3;
    }
    for (int idx = tid; idx < 384; idx += 256){
        int o = idx / 12, c = idx % 12;          // o = hidden k, c = out channel
        float v2v = 0.f, v4v = 0.f;
        if (c < 10){
            float s2 = g2[c] * rsqrtf(v2[c] + 1e-5f); v2v = w2[c * 32 + o] * s2;
            float s4 = g4[c] * rsqrtf(v4[c] + 1e-5f); v4v = w4[c * 32 + o] * s4;
        }
        g_fold[FBOFF + 1280 + idx] = v2v;
        g_fold[FBOFF + 1664 + idx] = v4v;
    }
    if (tid < 32){
        float s1 = g1[tid] * rsqrtf(v1[tid] + 1e-5f);
        g_fold[FBOFF + 2048 + tid] = b1[tid] - m1[tid] * s1;
        float s3 = g3[tid] * rsqrtf(v3[tid] + 1e-5f);
        g_fold[FBOFF + 2080 + tid] = b3[tid] - m3[tid] * s3;
    } else if (tid < 44){
        int c = tid - 32;
        float val = 0.f;
        if (c < 10){ float s = g2[c]*rsqrtf(v2[c] + 1e-5f); val = b2[c] - m2[c]*s; }
        g_fold[FBOFF + 2112 + c] = val;
    } else if (tid < 56){
        int c = tid - 44;
        float val = 0.f;
        if (c < 10){ float s = g4[c]*rsqrtf(v4[c] + 1e-5f); val = b4[c] - m4[c]*s; }
        g_fold[FBOFF + 2124 + c] = val;
    }
}

// ---------------------------------------------------------------------------
// common helpers
// ---------------------------------------------------------------------------
__device__ __forceinline__ uint32_t s2u(const void* p){
    uint32_t a;
    asm("{ .reg .u64 t; cvta.to.shared.u64 t, %1; cvt.u32.u64 %0, t; }" : "=r"(a) : "l"(p));
    return a;
}
__device__ __forceinline__ float2 ffma2(float2 a, float2 b, float2 c) {
    float2 d;
    asm("{\n\t"
        ".reg .b64 ra, rb, rc;\n\t"
        "mov.b64 ra, {%2, %3};\n\t"
        "mov.b64 rb, {%4, %5};\n\t"
        "mov.b64 rc, {%6, %7};\n\t"
        "fma.rn.f32x2 rc, ra, rb, rc;\n\t"
        "mov.b64 {%0, %1}, rc;\n\t"
        "}"
        : "=f"(d.x), "=f"(d.y)
        : "f"(a.x), "f"(a.y), "f"(b.x), "f"(b.y), "f"(c.x), "f"(c.y));
    return d;
}

// conv2 for BOTH pixels sharing each weight LDS: 96 LDS -> 320 ffma2
__device__ __forceinline__ void conv2_pair(const float* __restrict__ he,
                                           const float* __restrict__ ho,
                                           const float* __restrict__ ws,
                                           const float* __restrict__ bs,
                                           float* __restrict__ oe,
                                           float* __restrict__ oo){
    float2 ae[5], ao[5];
#pragma unroll
    for (int n = 0; n < 5; n++){
        float2 bb = *reinterpret_cast<const float2*>(bs + 2*n);
        ae[n] = bb; ao[n] = bb;
    }
#pragma unroll
    for (int k = 0; k < 32; k++){
        const float* r = ws + k * 12;
        float4 wa = *reinterpret_cast<const float4*>(r);
        float4 wb = *reinterpret_cast<const float4*>(r + 4);
        float2 wc = *reinterpret_cast<const float2*>(r + 8);
        float2 hbe = make_float2(he[k], he[k]);
        float2 hbo = make_float2(ho[k], ho[k]);
        float2 w0 = make_float2(wa.x, wa.y), w1 = make_float2(wa.z, wa.w);
        float2 w2 = make_float2(wb.x, wb.y), w3 = make_float2(wb.z, wb.w);
        ae[0] = ffma2(w0, hbe, ae[0]);  ao[0] = ffma2(w0, hbo, ao[0]);
        ae[1] = ffma2(w1, hbe, ae[1]);  ao[1] = ffma2(w1, hbo, ao[1]);
        ae[2] = ffma2(w2, hbe, ae[2]);  ao[2] = ffma2(w2, hbo, ao[2]);
        ae[3] = ffma2(w3, hbe, ae[3]);  ao[3] = ffma2(w3, hbo, ao[3]);
        ae[4] = ffma2(wc, hbe, ae[4]);  ao[4] = ffma2(wc, hbo, ao[4]);
    }
#pragma unroll
    for (int n = 0; n < 5; n++){
        oe[2*n] = fmaxf(ae[n].x, 0.f); oe[2*n+1] = fmaxf(ae[n].y, 0.f);
        oo[2*n] = fmaxf(ao[n].x, 0.f); oo[2*n+1] = fmaxf(ao[n].y, 0.f);
    }
}

#if HAS_TCGEN05
// ---------------------------------------------------------------------------
// tcgen05 helpers (sm_103a-only pass)
// ---------------------------------------------------------------------------
__device__ __forceinline__ uint64_t sdesc(uint32_t addr){
    return 0x4000404000010000ULL | (uint64_t)((addr >> 4) & 0x3FFF);
}
__device__ __forceinline__ void mma_tf32(uint32_t d, uint64_t a, uint64_t b, uint32_t idesc, uint32_t en){
    asm volatile("{\n\t"
        ".reg .pred p;\n\t"
        "setp.ne.u32 p, %4, 0;\n\t"
        "tcgen05.mma.cta_group::1.kind::tf32 [%0], %1, %2, %3, {%5, %5, %5, %5}, p;\n\t"
        "}"
        :: "r"(d), "l"(a), "l"(b), "r"(idesc), "r"(en), "r"(0u) : "memory");
}
__device__ __forceinline__ void issue_stage3(uint32_t d, uint64_t ah, uint64_t al,
                                             uint64_t bh, uint64_t bl, uint32_t idesc){
    uint32_t en = 0;
#pragma unroll
    for (int k = 0; k < 3; k++){ mma_tf32(d, ah + 2*k, bh + 2*k, idesc, en); en = 1; }
#pragma unroll
    for (int k = 0; k < 3; k++)  mma_tf32(d, ah + 2*k, bl + 2*k, idesc, 1);
#pragma unroll
    for (int k = 0; k < 3; k++)  mma_tf32(d, al + 2*k, bh + 2*k, idesc, 1);
}
__device__ __forceinline__ void tc_commit(uint32_t mbar){
    asm volatile("tcgen05.commit.cta_group::1.mbarrier::arrive::one.shared::cluster.b64 [%0];"
                 :: "r"(mbar) : "memory");
}
__device__ __forceinline__ void mbar_wait(uint32_t mbar, uint32_t ph){
    asm volatile("{\n\t"
        ".reg .pred P;\n\t"
        "LW%=:\n\t"
        "mbarrier.try_wait.parity.acquire.cta.shared::cta.b64 P, [%0], %1, 0x989680;\n\t"
        "@P bra LD%=;\n\t"
        "bra LW%=;\n\t"
        "LD%=:\n\t"
        "}" :: "r"(mbar), "r"(ph) : "memory");
}
__device__ __forceinline__ void fence_proxy(){ asm volatile("fence.proxy.async.shared::cta;" ::: "memory"); }
__device__ __forceinline__ void tc_fence_after(){ asm volatile("tcgen05.fence::after_thread_sync;" ::: "memory"); }
__device__ __forceinline__ void tc_fence_before(){ asm volatile("tcgen05.fence::before_thread_sync;" ::: "memory"); }
__device__ __forceinline__ void tc_wait_ld(){ asm volatile("tcgen05.wait::ld.sync.aligned;" ::: "memory"); }
__device__ __forceinline__ void wg_bar(int id){ asm volatile("bar.sync %0, 128;" :: "r"(id) : "memory"); }

__device__ __forceinline__ void ldtm32(uint32_t a, uint32_t* r){
    asm volatile("tcgen05.ld.sync.aligned.32x32b.x32.b32 "
        "{%0,%1,%2,%3,%4,%5,%6,%7,%8,%9,%10,%11,%12,%13,%14,%15,"
        "%16,%17,%18,%19,%20,%21,%22,%23,%24,%25,%26,%27,%28,%29,%30,%31}, [%32];"
        : "=r"(r[0]),"=r"(r[1]),"=r"(r[2]),"=r"(r[3]),"=r"(r[4]),"=r"(r[5]),"=r"(r[6]),"=r"(r[7]),
          "=r"(r[8]),"=r"(r[9]),"=r"(r[10]),"=r"(r[11]),"=r"(r[12]),"=r"(r[13]),"=r"(r[14]),"=r"(r[15]),
          "=r"(r[16]),"=r"(r[17]),"=r"(r[18]),"=r"(r[19]),"=r"(r[20]),"=r"(r[21]),"=r"(r[22]),"=r"(r[23]),
          "=r"(r[24]),"=r"(r[25]),"=r"(r[26]),"=r"(r[27]),"=r"(r[28]),"=r"(r[29]),"=r"(r[30]),"=r"(r[31])
        : "r"(a));
}
__device__ __forceinline__ void sts4(uint32_t a, float x, float y, float z, float w){
    asm volatile("st.shared.v4.b32 [%0], {%1,%2,%3,%4};" :: "r"(a),"f"(x),"f"(y),"f"(z),"f"(w) : "memory");
}
// 20 data cols + constant-1 bias col (20) + zero pad (21..23)
__device__ __forceinline__ void store24(uint32_t rowh, uint32_t rowl, int sx, const float* v){
#pragma unroll
    for (int g = 0; g < 5; g++){
        uint32_t off = (uint32_t)((g ^ sx) * 16);
        float h0 = tf32hi(v[4*g]),   h1 = tf32hi(v[4*g+1]);
        float h2 = tf32hi(v[4*g+2]), h3 = tf32hi(v[4*g+3]);
        sts4(rowh + off, h0, h1, h2, h3);
        sts4(rowl + off, v[4*g]-h0, v[4*g+1]-h1, v[4*g+2]-h2, v[4*g+3]-h3);
    }
    uint32_t off = (uint32_t)((5 ^ sx) * 16);
    sts4(rowh + off, 1.f, 0.f, 0.f, 0.f);
    sts4(rowl + off, 0.f, 0.f, 0.f, 0.f);
}
#else
// ---------------------------------------------------------------------------
// fallback helper: round-2 fused block (2 pixels, ffma2)
// ---------------------------------------------------------------------------
__device__ __forceinline__ void run_block_fb(
    const float2 (&xb)[2][20],
    const float* __restrict__ sWt, const float* __restrict__ sBa,
    const float* __restrict__ sW2, const float* __restrict__ sBb,
    float2 (&out2)[5][2])
{
#pragma unroll
    for (int cp = 0; cp < 5; cp++) {
        float2 bb = *reinterpret_cast<const float2*>(sBb + 2 * cp);
        out2[cp][0] = bb; out2[cp][1] = bb;
    }
#pragma unroll
    for (int ob = 0; ob < 32; ob += 4) {
        float2 b01 = *reinterpret_cast<const float2*>(sBa + ob);
        float2 b23 = *reinterpret_cast<const float2*>(sBa + ob + 2);
        float2 a00 = b01, a01 = b01, a10 = b23, a11 = b23;
#pragma unroll
        for (int c = 0; c < 20; c++) {
            float4 w = *reinterpret_cast<const float4*>(sWt + c * 32 + ob);
            float2 w01 = make_float2(w.x, w.y);
            float2 w23 = make_float2(w.z, w.w);
            a00 = ffma2(w01, xb[0][c], a00);
            a01 = ffma2(w01, xb[1][c], a01);
            a10 = ffma2(w23, xb[0][c], a10);
            a11 = ffma2(w23, xb[1][c], a11);
        }
        a00.x = fmaxf(a00.x, 0.f); a00.y = fmaxf(a00.y, 0.f);
        a01.x = fmaxf(a01.x, 0.f); a01.y = fmaxf(a01.y, 0.f);
        a10.x = fmaxf(a10.x, 0.f); a10.y = fmaxf(a10.y, 0.f);
        a11.x = fmaxf(a11.x, 0.f); a11.y = fmaxf(a11.y, 0.f);
#pragma unroll
        for (int j = 0; j < 4; j++) {
            float h0 = (j == 0) ? a00.x : (j == 1) ? a00.y : (j == 2) ? a10.x : a10.y;
            float h1 = (j == 0) ? a01.x : (j == 1) ? a01.y : (j == 2) ? a11.x : a11.y;
            float2 hb0 = make_float2(h0, h0);
            float2 hb1 = make_float2(h1, h1);
            const float* r = sW2 + (ob + j) * 12;
            float4 wa = *reinterpret_cast<const float4*>(r);
            float4 wb = *reinterpret_cast<const float4*>(r + 4);
            float2 wc = *reinterpret_cast<const float2*>(r + 8);
            float2 w0 = make_float2(wa.x, wa.y);
            float2 w1 = make_float2(wa.z, wa.w);
            float2 w2 = make_float2(wb.x, wb.y);
            float2 w3 = make_float2(wb.z, wb.w);
            out2[0][0] = ffma2(w0, hb0, out2[0][0]); out2[0][1] = ffma2(w0, hb1, out2[0][1]);
            out2[1][0] = ffma2(w1, hb0, out2[1][0]); out2[1][1] = ffma2(w1, hb1, out2[1][1]);
            out2[2][0] = ffma2(w2, hb0, out2[2][0]); out2[2][1] = ffma2(w2, hb1, out2[2][1]);
            out2[3][0] = ffma2(w3, hb0, out2[3][0]); out2[3][1] = ffma2(w3, hb1, out2[3][1]);
            out2[4][0] = ffma2(wc, hb0, out2[4][0]); out2[4][1] = ffma2(wc, hb1, out2[4][1]);
        }
    }
#pragma unroll
    for (int cp = 0; cp < 5; cp++) {
        out2[cp][0].x = fmaxf(out2[cp][0].x, 0.f); out2[cp][0].y = fmaxf(out2[cp][0].y, 0.f);
        out2[cp][1].x = fmaxf(out2[cp][1].x, 0.f); out2[cp][1].y = fmaxf(out2[cp][1].y, 0.f);
    }
}
#endif

// ---------------------------------------------------------------------------
// fused kernel: 256-px supertile per wg, 2 adjacent px per thread.
// conv1 on tcgen05 (2 x M=128 MMAs, ONE commit per stage), conv2 on FMA pipe.
// SMEM: 0 tmem ptr; 8..56 mbar[6]; floats[256..6232) params;
//       26624 + wg*65536: X buffers [Xeh|Xel|Xoh|Xol] 4x16KB
// ---------------------------------------------------------------------------
__global__ void __launch_bounds__(384, 1) fused_kernel(
    const float* __restrict__ xf, const float* __restrict__ xh1,
    const float* __restrict__ xh2, float* __restrict__ out)
{
#if HAS_TCGEN05
    extern __shared__ char smem[];
    float* sf = (float*)smem;
    uint32_t sb = s2u(smem);
    int tid = threadIdx.x;
    int wg  = tid >> 7;
    int wt  = tid & 127;

    for (int i = tid; i < 5120; i += 384) sf[256 + i] = g_fold[256 + i];
    for (int i = tid; i < 856; i += 384)  sf[5376 + i] = g_fold[FBOFF + 1280 + i];

    if (tid < 32){
        asm volatile("tcgen05.alloc.cta_group::1.sync.aligned.shared::cta.b32 [%0], %1;"
                     :: "r"(sb), "r"(512u) : "memory");
        asm volatile("tcgen05.relinquish_alloc_permit.cta_group::1.sync.aligned;" ::: "memory");
    }
    if (tid >= 32 && tid < 38){
        uint32_t mb = sb + 8 + (uint32_t)(tid - 32) * 8;
        asm volatile("mbarrier.init.shared.b64 [%0], %1;" :: "r"(mb), "r"(1u) : "memory");
    }
    fence_proxy();
    __syncthreads();
    uint32_t tmem;
    asm volatile("ld.shared.b32 %0, [%1];" : "=r"(tmem) : "r"(sb));

    const float* w2s = sf + 5376;   // [32][12]
    const float* w4s = sf + 5760;
    const float* b2s = sf + 6208;
    const float* b4s = sf + 6220;

    uint32_t mb1 = sb + 8 + (uint32_t)(wg * 2) * 8;
    uint32_t mb2 = mb1 + 8;
    uint32_t base = sb + 26624 + (uint32_t)wg * 65536;
    uint32_t bEh = base,          bEl = base + 16384;
    uint32_t bOh = base + 32768,  bOl = base + 49152;
    uint64_t dEh = sdesc(bEh), dEl = sdesc(bEl);
    uint64_t dOh = sdesc(bOh), dOl = sdesc(bOl);
    uint64_t dW1h = sdesc(sb + 1024),  dW1l = sdesc(sb + 5120);
    uint64_t dW3h = sdesc(sb + 13312), dW3l = sdesc(sb + 17408);
    const uint32_t ID32 = (1u<<4) | (2u<<7) | (2u<<10) | (4u<<17) | (8u<<24);
    uint32_t tmw = tmem + (uint32_t)wg * 128;
    uint32_t ph1 = 0, ph2 = 0;
    int bid = wg + 1;
    uint32_t rEh = bEh + (uint32_t)wt * 128, rEl = bEl + (uint32_t)wt * 128;
    uint32_t rOh = bOh + (uint32_t)wt * 128, rOl = bOl + (uint32_t)wt * 128;
    int sx = wt & 7;
    const int STRIDE = 444;

    int s0 = blockIdx.x * 3 + wg;
    size_t gb = (size_t)(s0 >> 10) * CHW + (size_t)((s0 & 1023) << 8) + (size_t)(2 * wt);

    // prologue: load x(s0) -> X, issue stage1
    float fae[10], fao[10];
    {
        float xe[20], xo[20];
#pragma unroll
        for (int c = 0; c < 10; c++){
            float2 v = *reinterpret_cast<const float2*>(xh1 + gb + (size_t)c * HW);
            xe[c] = v.x; xo[c] = v.y;
        }
#pragma unroll
        for (int c = 0; c < 10; c++){
            float2 v = *reinterpret_cast<const float2*>(xh2 + gb + (size_t)c * HW);
            xe[10+c] = v.x; xo[10+c] = v.y;
        }
#pragma unroll
        for (int c = 0; c < 10; c++){
            float2 v = *reinterpret_cast<const float2*>(xf + gb + (size_t)c * HW);
            fae[c] = v.x; fao[c] = v.y;
        }
        store24(rEh, rEl, sx, xe);
        store24(rOh, rOl, sx, xo);
        fence_proxy();
        wg_bar(bid);
        if (wt == 0){
            tc_fence_after();
            issue_stage3(tmw,      dEh, dEl, dW1h, dW1l, ID32);
            issue_stage3(tmw + 32, dOh, dOl, dW1h, dW1l, ID32);
            tc_commit(mb1);
        }
    }

    for (int s = s0; s < NSUP; s += STRIDE){
        int sn = s + STRIDE;
        bool hasNext = sn < NSUP;
        int sl = hasNext ? sn : s;
        size_t gbn = (size_t)(sl >> 10) * CHW + (size_t)((sl & 1023) << 8) + (size_t)(2 * wt);

        // ---- epi1: conv2 for both pixels, msg out ----
        float msge[10], msgo[10];
        mbar_wait(mb1, ph1); ph1 ^= 1;
        tc_fence_after();
        {
            uint32_t de[32], dox[32];
            ldtm32(tmw, de); ldtm32(tmw + 32, dox);
            tc_wait_ld(); tc_fence_before();
            float he[32], ho[32];
#pragma unroll
            for (int j = 0; j < 32; j++){
                he[j] = fmaxf(__uint_as_float(de[j]), 0.f);
                ho[j] = fmaxf(__uint_as_float(dox[j]), 0.f);
            }
            conv2_pair(he, ho, w2s, b2s, msge, msgo);
        }
#pragma unroll
        for (int j = 0; j < 10; j++)
            *reinterpret_cast<float2*>(out + MSGOFF + gb + (size_t)j * HW) = make_float2(msge[j], msgo[j]);

        // ---- refill X := (xf, msg); issue stage2 ----
        {
            float ve[20], vo[20];
#pragma unroll
            for (int c = 0; c < 10; c++){
                ve[c] = fae[c]; ve[10+c] = msge[c];
                vo[c] = fao[c]; vo[10+c] = msgo[c];
            }
            store24(rEh, rEl, sx, ve);
            store24(rOh, rOl, sx, vo);
        }
        fence_proxy();
        wg_bar(bid);
        if (wt == 0){
            tc_fence_after();
            issue_stage3(tmw + 64, dEh, dEl, dW3h, dW3l, ID32);
            issue_stage3(tmw + 96, dOh, dOl, dW3h, dW3l, ID32);
            tc_commit(mb2);
        }

        // ---- prefetch next tile (overlaps stage2 MMA) ----
        float xne[20], xno[20], fne[10], fno[10];
#pragma unroll
        for (int c = 0; c < 10; c++){
            float2 v = *reinterpret_cast<const float2*>(xh1 + gbn + (size_t)c * HW);
            xne[c] = v.x; xno[c] = v.y;
        }
#pragma unroll
        for (int c = 0; c < 10; c++){
            float2 v = *reinterpret_cast<const float2*>(xh2 + gbn + (size_t)c * HW);
            xne[10+c] = v.x; xno[10+c] = v.y;
        }
#pragma unroll
        for (int c = 0; c < 10; c++){
            float2 v = *reinterpret_cast<const float2*>(xf + gbn + (size_t)c * HW);
            fne[c] = v.x; fno[c] = v.y;
        }

        // ---- wait stage2 done reading X, refill X := x(t+1), issue stage1(t+1) ----
        mbar_wait(mb2, ph2); ph2 ^= 1;
        tc_fence_after();
        store24(rEh, rEl, sx, xne);
        store24(rOh, rOl, sx, xno);
        fence_proxy();
        wg_bar(bid);
        if (wt == 0 && hasNext){
            tc_fence_after();
            issue_stage3(tmw,      dEh, dEl, dW1h, dW1l, ID32);
            issue_stage3(tmw + 32, dOh, dOl, dW1h, dW1l, ID32);
            tc_commit(mb1);
        }

        // ---- epi2: xf_new out (overlaps stage1(t+1) MMA) ----
        {
            uint32_t de[32], dox[32];
            ldtm32(tmw + 64, de); ldtm32(tmw + 96, dox);
            tc_wait_ld(); tc_fence_before();
            float he[32], ho[32];
#pragma unroll
            for (int j = 0; j < 32; j++){
                he[j] = fmaxf(__uint_as_float(de[j]), 0.f);
                ho[j] = fmaxf(__uint_as_float(dox[j]), 0.f);
            }
            float rese[10], reso[10];
            conv2_pair(he, ho, w4s, b4s, rese, reso);
#pragma unroll
            for (int j = 0; j < 10; j++)
                *reinterpret_cast<float2*>(out + gb + (size_t)j * HW) = make_float2(rese[j], reso[j]);
        }

        gb = gbn;
#pragma unroll
        for (int c = 0; c < 10; c++){ fae[c] = fne[c]; fao[c] = fno[c]; }
    }

    __syncthreads();
    if (tid < 32){
        asm volatile("tcgen05.dealloc.cta_group::1.sync.aligned.b32 %0, %1;" :: "r"(tmem), "r"(512u));
    }
#else
    // ------------------- fallback: round-2 ffma2 path -------------------
    extern __shared__ char smem[];
    float* sf = (float*)smem;
    {
        const float4* src = reinterpret_cast<const float4*>(g_fold + FBOFF);
        float4* dst = reinterpret_cast<float4*>(sf);
        for (int i = threadIdx.x; i < 534; i += 384) dst[i] = src[i];
    }
    __syncthreads();
    const float* sW1t = sf;
    const float* sW3t = sf + 640;
    const float* sW2f = sf + 1280;
    const float* sW4f = sf + 1664;
    const float* sB1  = sf + 2048;
    const float* sB3  = sf + 2080;
    const float* sB2  = sf + 2112;
    const float* sB4  = sf + 2124;

    const int stride = gridDim.x * 384;
    for (int t = blockIdx.x * 384 + threadIdx.x; t < 1048576; t += stride){
        int b  = t >> 17;
        int hw = (t & 0x1FFFF) << 1;
        size_t base = (size_t)b * CHW + hw;
        const float* ph1 = xh1 + base;
        const float* ph2 = xh2 + base;
        const float* pf  = xf  + base;
        float* po_new = out + base;
        float* po_msg = out + (size_t)MSGOFF + base;

        float2 xb[2][20];
#pragma unroll
        for (int c = 0; c < 10; c++) {
            float2 v = *reinterpret_cast<const float2*>(ph1 + (size_t)c * HW);
            xb[0][c] = make_float2(v.x, v.x);
            xb[1][c] = make_float2(v.y, v.y);
        }
#pragma unroll
        for (int c = 0; c < 10; c++) {
            float2 v = *reinterpret_cast<const float2*>(ph2 + (size_t)c * HW);
            xb[0][10 + c] = make_float2(v.x, v.x);
            xb[1][10 + c] = make_float2(v.y, v.y);
        }

        float2 msg2[5][2];
        run_block_fb(xb, sW1t, sB1, sW2f, sB2, msg2);

#pragma unroll
        for (int cp = 0; cp < 5; cp++) {
            float2 m0 = msg2[cp][0], m1 = msg2[cp][1];
            *reinterpret_cast<float2*>(po_msg + (size_t)(2 * cp)     * HW) = make_float2(m0.x, m1.x);
            *reinterpret_cast<float2*>(po_msg + (size_t)(2 * cp + 1) * HW) = make_float2(m0.y, m1.y);
            xb[0][10 + 2 * cp]     = make_float2(m0.x, m0.x);
            xb[0][10 + 2 * cp + 1] = make_float2(m0.y, m0.y);
            xb[1][10 + 2 * cp]     = make_float2(m1.x, m1.x);
            xb[1][10 + 2 * cp + 1] = make_float2(m1.y, m1.y);
        }
#pragma unroll
        for (int c = 0; c < 10; c++) {
            float2 v = *reinterpret_cast<const float2*>(pf + (size_t)c * HW);
            xb[0][c] = make_float2(v.x, v.x);
            xb[1][c] = make_float2(v.y, v.y);
        }

        float2 r2[5][2];
        run_block_fb(xb, sW3t, sB3, sW4f, sB4, r2);

#pragma unroll
        for (int cp = 0; cp < 5; cp++) {
            float2 r0 = r2[cp][0], r1 = r2[cp][1];
            *reinterpret_cast<float2*>(po_new + (size_t)(2 * cp)     * HW) = make_float2(r0.x, r1.x);
            *reinterpret_cast<float2*>(po_new + (size_t)(2 * cp + 1) * HW) = make_float2(r0.y, r1.y);
        }
    }
#endif
}

extern "C" void kernel_launch(void* const* d_in, const int* in_sizes, int n_in,
                              void* d_out, int out_size) {
    const float* xf  = (const float*)d_in[0];
    const float* xh1 = (const float*)d_in[1];
    const float* xh2 = (const float*)d_in[2];

    fold_kernel<<<1, 256>>>(
        (const float*)d_in[3],  (const float*)d_in[4],  (const float*)d_in[5],
        (const float*)d_in[6],  (const float*)d_in[7],
        (const float*)d_in[8],  (const float*)d_in[9],  (const float*)d_in[10],
        (const float*)d_in[11], (const float*)d_in[12],
        (const float*)d_in[13], (const float*)d_in[14], (const float*)d_in[15],
        (const float*)d_in[16], (const float*)d_in[17],
        (const float*)d_in[18], (const float*)d_in[19], (const float*)d_in[20],
        (const float*)d_in[21], (const float*)d_in[22]);

    cudaFuncSetAttribute(fused_kernel, cudaFuncAttributeMaxDynamicSharedMemorySize, 223232);
    fused_kernel<<<148, 384, 223232>>>(xf, xh1, xh2, (float*)d_out);
}

// round 15
// speedup vs baseline: 1.5846x; 1.2562x over previous
#include <cuda_runtime.h>
#include <cstdint>

#define HW 262144
#define CHW 2621440          // 10*HW
#define MSGOFF 20971520      // 8*10*HW
#define NSUP 8192            // 256-pixel supertiles

#if defined(__CUDA_ARCH_FEAT_SM103_ALL) || defined(__CUDA_ARCH_FEAT_SM100_ALL) || \
    (defined(__CUDA_ARCH_SPECIFIC__) && (__CUDA_ARCH_SPECIFIC__ >= 1000))
#define HAS_TCGEN05 1
#else
#define HAS_TCGEN05 0
#endif

// g_fold float layout:
//  [16,6400)  tcgen05 swizzled tiles:
//    256 W1hi[32x32 SW128] (row k=20 = folded bias1) ; 1280 W1lo
//    3328 W3hi ; 4352 W3lo
//  [6400,8536) fallback / stage-2 params:
//    +0 W1t 640 ; +640 W3t 640 ; +1280 W2f[k=32][n pad12] 384 ; +1664 W4f 384
//    +2048 B1 32 ; +2080 B3 32 ; +2112 B2 12 ; +2124 B4 12
#define FBOFF 6400
__device__ float g_fold[8544];

__device__ __forceinline__ float tf32hi(float x){
    return __uint_as_float(__float_as_uint(x) & 0xFFFFE000u);
}

// ---------------------------------------------------------------------------
// prep kernel
// ---------------------------------------------------------------------------
__global__ void fold_kernel(
    const float* __restrict__ w1,const float* __restrict__ g1,const float* __restrict__ b1,const float* __restrict__ m1,const float* __restrict__ v1,
    const float* __restrict__ w2,const float* __restrict__ g2,const float* __restrict__ b2,const float* __restrict__ m2,const float* __restrict__ v2,
    const float* __restrict__ w3,const float* __restrict__ g3,const float* __restrict__ b3,const float* __restrict__ m3,const float* __restrict__ v3,
    const float* __restrict__ w4,const float* __restrict__ g4,const float* __restrict__ b4,const float* __restrict__ m4,const float* __restrict__ v4)
{
    int tid = threadIdx.x;
    for (int i = tid; i < 1024; i += 256){       // W1 (32 rows o, 32 cols k)
        int o = i >> 5, k = i & 31;
        float s = g1[o] * rsqrtf(v1[o] + 1e-5f);
        float v = 0.f;
        if (k < 20) v = w1[o*20 + k] * s;
        else if (k == 20) v = b1[o] - m1[o]*s;
        int byo = o*128 + k*4;
        int sw = byo ^ ((byo >> 3) & 0x70);
        float h = tf32hi(v);
        g_fold[256  + (sw >> 2)] = h;
        g_fold[1280 + (sw >> 2)] = v - h;
    }
    for (int i = tid; i < 1024; i += 256){       // W3
        int o = i >> 5, k = i & 31;
        float s = g3[o] * rsqrtf(v3[o] + 1e-5f);
        float v = 0.f;
        if (k < 20) v = w3[o*20 + k] * s;
        else if (k == 20) v = b3[o] - m3[o]*s;
        int byo = o*128 + k*4;
        int sw = byo ^ ((byo >> 3) & 0x70);
        float h = tf32hi(v);
        g_fold[3328 + (sw >> 2)] = h;
        g_fold[4352 + (sw >> 2)] = v - h;
    }
    // fallback / stage-2 layouts
    for (int idx = tid; idx < 640; idx += 256){
        int c = idx >> 5, o = idx & 31;
        float s1 = g1[o] * rsqrtf(v1[o] + 1e-5f);
        g_fold[FBOFF + idx] = w1[o * 20 + c] * s1;
        float s3 = g3[o] * rsqrtf(v3[o] + 1e-5f);
        g_fold[FBOFF + 640 + idx] = w3[o * 20 + c] * s3;
    }
    for (int idx = tid; idx < 384; idx += 256){
        int o = idx / 12, c = idx % 12;          // o = hidden k, c = out channel
        float v2v = 0.f, v4v = 0.f;
        if (c < 10){
            float s2 = g2[c] * rsqrtf(v2[c] + 1e-5f); v2v = w2[c * 32 + o] * s2;
            float s4 = g4[c] * rsqrtf(v4[c] + 1e-5f); v4v = w4[c * 32 + o] * s4;
        }
        g_fold[FBOFF + 1280 + idx] = v2v;
        g_fold[FBOFF + 1664 + idx] = v4v;
    }
    if (tid < 32){
        float s1 = g1[tid] * rsqrtf(v1[tid] + 1e-5f);
        g_fold[FBOFF + 2048 + tid] = b1[tid] - m1[tid] * s1;
        float s3 = g3[tid] * rsqrtf(v3[tid] + 1e-5f);
        g_fold[FBOFF + 2080 + tid] = b3[tid] - m3[tid] * s3;
    } else if (tid < 44){
        int c = tid - 32;
        float val = 0.f;
        if (c < 10){ float s = g2[c]*rsqrtf(v2[c] + 1e-5f); val = b2[c] - m2[c]*s; }
        g_fold[FBOFF + 2112 + c] = val;
    } else if (tid < 56){
        int c = tid - 44;
        float val = 0.f;
        if (c < 10){ float s = g4[c]*rsqrtf(v4[c] + 1e-5f); val = b4[c] - m4[c]*s; }
        g_fold[FBOFF + 2124 + c] = val;
    }
}

// ---------------------------------------------------------------------------
// common helpers
// ---------------------------------------------------------------------------
__device__ __forceinline__ uint32_t s2u(const void* p){
    uint32_t a;
    asm("{ .reg .u64 t; cvta.to.shared.u64 t, %1; cvt.u32.u64 %0, t; }" : "=r"(a) : "l"(p));
    return a;
}
__device__ __forceinline__ float2 ffma2(float2 a, float2 b, float2 c) {
    float2 d;
    asm("{\n\t"
        ".reg .b64 ra, rb, rc;\n\t"
        "mov.b64 ra, {%2, %3};\n\t"
        "mov.b64 rb, {%4, %5};\n\t"
        "mov.b64 rc, {%6, %7};\n\t"
        "fma.rn.f32x2 rc, ra, rb, rc;\n\t"
        "mov.b64 {%0, %1}, rc;\n\t"
        "}"
        : "=f"(d.x), "=f"(d.y)
        : "f"(a.x), "f"(a.y), "f"(b.x), "f"(b.y), "f"(c.x), "f"(c.y));
    return d;
}

// conv2 for BOTH pixels sharing each weight LDS: 96 LDS -> 320 ffma2
__device__ __forceinline__ void conv2_pair(const float* __restrict__ he,
                                           const float* __restrict__ ho,
                                           const float* __restrict__ ws,
                                           const float* __restrict__ bs,
                                           float* __restrict__ oe,
                                           float* __restrict__ oo){
    float2 ae[5], ao[5];
#pragma unroll
    for (int n = 0; n < 5; n++){
        float2 bb = *reinterpret_cast<const float2*>(bs + 2*n);
        ae[n] = bb; ao[n] = bb;
    }
#pragma unroll
    for (int k = 0; k < 32; k++){
        const float* r = ws + k * 12;
        float4 wa = *reinterpret_cast<const float4*>(r);
        float4 wb = *reinterpret_cast<const float4*>(r + 4);
        float2 wc = *reinterpret_cast<const float2*>(r + 8);
        float2 hbe = make_float2(he[k], he[k]);
        float2 hbo = make_float2(ho[k], ho[k]);
        float2 w0 = make_float2(wa.x, wa.y), w1 = make_float2(wa.z, wa.w);
        float2 w2 = make_float2(wb.x, wb.y), w3 = make_float2(wb.z, wb.w);
        ae[0] = ffma2(w0, hbe, ae[0]);  ao[0] = ffma2(w0, hbo, ao[0]);
        ae[1] = ffma2(w1, hbe, ae[1]);  ao[1] = ffma2(w1, hbo, ao[1]);
        ae[2] = ffma2(w2, hbe, ae[2]);  ao[2] = ffma2(w2, hbo, ao[2]);
        ae[3] = ffma2(w3, hbe, ae[3]);  ao[3] = ffma2(w3, hbo, ao[3]);
        ae[4] = ffma2(wc, hbe, ae[4]);  ao[4] = ffma2(wc, hbo, ao[4]);
    }
#pragma unroll
    for (int n = 0; n < 5; n++){
        oe[2*n] = fmaxf(ae[n].x, 0.f); oe[2*n+1] = fmaxf(ae[n].y, 0.f);
        oo[2*n] = fmaxf(ao[n].x, 0.f); oo[2*n+1] = fmaxf(ao[n].y, 0.f);
    }
}

#if HAS_TCGEN05
// ---------------------------------------------------------------------------
// tcgen05 helpers (sm_103a-only pass)
// ---------------------------------------------------------------------------
__device__ __forceinline__ uint64_t sdesc(uint32_t addr){
    return 0x4000404000010000ULL | (uint64_t)((addr >> 4) & 0x3FFF);
}
__device__ __forceinline__ void mma_tf32(uint32_t d, uint64_t a, uint64_t b, uint32_t idesc, uint32_t en){
    asm volatile("{\n\t"
        ".reg .pred p;\n\t"
        "setp.ne.u32 p, %4, 0;\n\t"
        "tcgen05.mma.cta_group::1.kind::tf32 [%0], %1, %2, %3, {%5, %5, %5, %5}, p;\n\t"
        "}"
        :: "r"(d), "l"(a), "l"(b), "r"(idesc), "r"(en), "r"(0u) : "memory");
}
// 2-term: A raw fp32 (HW-truncated to tf32), W split hi/lo -> 6 MMAs
__device__ __forceinline__ void issue_stage2t(uint32_t d, uint64_t a,
                                              uint64_t bh, uint64_t bl, uint32_t idesc){
    uint32_t en = 0;
#pragma unroll
    for (int k = 0; k < 3; k++){ mma_tf32(d, a + 2*k, bh + 2*k, idesc, en); en = 1; }
#pragma unroll
    for (int k = 0; k < 3; k++)  mma_tf32(d, a + 2*k, bl + 2*k, idesc, 1);
}
__device__ __forceinline__ void tc_commit(uint32_t mbar){
    asm volatile("tcgen05.commit.cta_group::1.mbarrier::arrive::one.shared::cluster.b64 [%0];"
                 :: "r"(mbar) : "memory");
}
__device__ __forceinline__ void mbar_wait(uint32_t mbar, uint32_t ph){
    asm volatile("{\n\t"
        ".reg .pred P;\n\t"
        "LW%=:\n\t"
        "mbarrier.try_wait.parity.acquire.cta.shared::cta.b64 P, [%0], %1, 0x989680;\n\t"
        "@P bra LD%=;\n\t"
        "bra LW%=;\n\t"
        "LD%=:\n\t"
        "}" :: "r"(mbar), "r"(ph) : "memory");
}
__device__ __forceinline__ void fence_proxy(){ asm volatile("fence.proxy.async.shared::cta;" ::: "memory"); }
__device__ __forceinline__ void tc_fence_after(){ asm volatile("tcgen05.fence::after_thread_sync;" ::: "memory"); }
__device__ __forceinline__ void tc_fence_before(){ asm volatile("tcgen05.fence::before_thread_sync;" ::: "memory"); }
__device__ __forceinline__ void tc_wait_ld(){ asm volatile("tcgen05.wait::ld.sync.aligned;" ::: "memory"); }
__device__ __forceinline__ void wg_bar(int id){ asm volatile("bar.sync %0, 128;" :: "r"(id) : "memory"); }

__device__ __forceinline__ void ldtm32(uint32_t a, uint32_t* r){
    asm volatile("tcgen05.ld.sync.aligned.32x32b.x32.b32 "
        "{%0,%1,%2,%3,%4,%5,%6,%7,%8,%9,%10,%11,%12,%13,%14,%15,"
        "%16,%17,%18,%19,%20,%21,%22,%23,%24,%25,%26,%27,%28,%29,%30,%31}, [%32];"
        : "=r"(r[0]),"=r"(r[1]),"=r"(r[2]),"=r"(r[3]),"=r"(r[4]),"=r"(r[5]),"=r"(r[6]),"=r"(r[7]),
          "=r"(r[8]),"=r"(r[9]),"=r"(r[10]),"=r"(r[11]),"=r"(r[12]),"=r"(r[13]),"=r"(r[14]),"=r"(r[15]),
          "=r"(r[16]),"=r"(r[17]),"=r"(r[18]),"=r"(r[19]),"=r"(r[20]),"=r"(r[21]),"=r"(r[22]),"=r"(r[23]),
          "=r"(r[24]),"=r"(r[25]),"=r"(r[26]),"=r"(r[27]),"=r"(r[28]),"=r"(r[29]),"=r"(r[30]),"=r"(r[31])
        : "r"(a));
}
__device__ __forceinline__ void sts4(uint32_t a, float x, float y, float z, float w){
    asm volatile("st.shared.v4.b32 [%0], {%1,%2,%3,%4};" :: "r"(a),"f"(x),"f"(y),"f"(z),"f"(w) : "memory");
}
// 20 data cols (raw fp32) + constant-1 bias col (20) + zero pad (21..23)
__device__ __forceinline__ void store24(uint32_t row, int sx, const float* v){
#pragma unroll
    for (int g = 0; g < 5; g++){
        uint32_t off = (uint32_t)((g ^ sx) * 16);
        sts4(row + off, v[4*g], v[4*g+1], v[4*g+2], v[4*g+3]);
    }
    sts4(row + (uint32_t)((5 ^ sx) * 16), 1.f, 0.f, 0.f, 0.f);
}
#else
// ---------------------------------------------------------------------------
// fallback helper: round-2 fused block (2 pixels, ffma2)
// ---------------------------------------------------------------------------
__device__ __forceinline__ void run_block_fb(
    const float2 (&xb)[2][20],
    const float* __restrict__ sWt, const float* __restrict__ sBa,
    const float* __restrict__ sW2, const float* __restrict__ sBb,
    float2 (&out2)[5][2])
{
#pragma unroll
    for (int cp = 0; cp < 5; cp++) {
        float2 bb = *reinterpret_cast<const float2*>(sBb + 2 * cp);
        out2[cp][0] = bb; out2[cp][1] = bb;
    }
#pragma unroll
    for (int ob = 0; ob < 32; ob += 4) {
        float2 b01 = *reinterpret_cast<const float2*>(sBa + ob);
        float2 b23 = *reinterpret_cast<const float2*>(sBa + ob + 2);
        float2 a00 = b01, a01 = b01, a10 = b23, a11 = b23;
#pragma unroll
        for (int c = 0; c < 20; c++) {
            float4 w = *reinterpret_cast<const float4*>(sWt + c * 32 + ob);
            float2 w01 = make_float2(w.x, w.y);
            float2 w23 = make_float2(w.z, w.w);
            a00 = ffma2(w01, xb[0][c], a00);
            a01 = ffma2(w01, xb[1][c], a01);
            a10 = ffma2(w23, xb[0][c], a10);
            a11 = ffma2(w23, xb[1][c], a11);
        }
        a00.x = fmaxf(a00.x, 0.f); a00.y = fmaxf(a00.y, 0.f);
        a01.x = fmaxf(a01.x, 0.f); a01.y = fmaxf(a01.y, 0.f);
        a10.x = fmaxf(a10.x, 0.f); a10.y = fmaxf(a10.y, 0.f);
        a11.x = fmaxf(a11.x, 0.f); a11.y = fmaxf(a11.y, 0.f);
#pragma unroll
        for (int j = 0; j < 4; j++) {
            float h0 = (j == 0) ? a00.x : (j == 1) ? a00.y : (j == 2) ? a10.x : a10.y;
            float h1 = (j == 0) ? a01.x : (j == 1) ? a01.y : (j == 2) ? a11.x : a11.y;
            float2 hb0 = make_float2(h0, h0);
            float2 hb1 = make_float2(h1, h1);
            const float* r = sW2 + (ob + j) * 12;
            float4 wa = *reinterpret_cast<const float4*>(r);
            float4 wb = *reinterpret_cast<const float4*>(r + 4);
            float2 wc = *reinterpret_cast<const float2*>(r + 8);
            float2 w0 = make_float2(wa.x, wa.y);
            float2 w1 = make_float2(wa.z, wa.w);
            float2 w2 = make_float2(wb.x, wb.y);
            float2 w3 = make_float2(wb.z, wb.w);
            out2[0][0] = ffma2(w0, hb0, out2[0][0]); out2[0][1] = ffma2(w0, hb1, out2[0][1]);
            out2[1][0] = ffma2(w1, hb0, out2[1][0]); out2[1][1] = ffma2(w1, hb1, out2[1][1]);
            out2[2][0] = ffma2(w2, hb0, out2[2][0]); out2[2][1] = ffma2(w2, hb1, out2[2][1]);
            out2[3][0] = ffma2(w3, hb0, out2[3][0]); out2[3][1] = ffma2(w3, hb1, out2[3][1]);
            out2[4][0] = ffma2(wc, hb0, out2[4][0]); out2[4][1] = ffma2(wc, hb1, out2[4][1]);
        }
    }
#pragma unroll
    for (int cp = 0; cp < 5; cp++) {
        out2[cp][0].x = fmaxf(out2[cp][0].x, 0.f); out2[cp][0].y = fmaxf(out2[cp][0].y, 0.f);
        out2[cp][1].x = fmaxf(out2[cp][1].x, 0.f); out2[cp][1].y = fmaxf(out2[cp][1].y, 0.f);
    }
}
#endif

// ---------------------------------------------------------------------------
// fused kernel: 256-px supertile per wg (4 wg), 2 adjacent px per thread.
// conv1 on tcgen05 (2-term tf32, 12 MMAs/stage, ONE commit), conv2 on FMA pipe.
// SMEM: 0 tmem ptr; 8..72 mbar[8]; floats[256..6232) params;
//       26624 + wg*32768: A buffers [E|O] 2x16KB (raw fp32, HW tf32-truncated)
// ---------------------------------------------------------------------------
__global__ void __launch_bounds__(512, 1) fused_kernel(
    const float* __restrict__ xf, const float* __restrict__ xh1,
    const float* __restrict__ xh2, float* __restrict__ out)
{
#if HAS_TCGEN05
    extern __shared__ char smem[];
    float* sf = (float*)smem;
    uint32_t sb = s2u(smem);
    int tid = threadIdx.x;
    int wg  = tid >> 7;
    int wt  = tid & 127;

    for (int i = tid; i < 5120; i += 512) sf[256 + i] = g_fold[256 + i];
    for (int i = tid; i < 856; i += 512)  sf[5376 + i] = g_fold[FBOFF + 1280 + i];

    if (tid < 32){
        asm volatile("tcgen05.alloc.cta_group::1.sync.aligned.shared::cta.b32 [%0], %1;"
                     :: "r"(sb), "r"(512u) : "memory");
        asm volatile("tcgen05.relinquish_alloc_permit.cta_group::1.sync.aligned;" ::: "memory");
    }
    if (tid >= 32 && tid < 40){
        uint32_t mb = sb + 8 + (uint32_t)(tid - 32) * 8;
        asm volatile("mbarrier.init.shared.b64 [%0], %1;" :: "r"(mb), "r"(1u) : "memory");
    }
    fence_proxy();
    __syncthreads();
    uint32_t tmem;
    asm volatile("ld.shared.b32 %0, [%1];" : "=r"(tmem) : "r"(sb));

    const float* w2s = sf + 5376;   // [32][12]
    const float* w4s = sf + 5760;
    const float* b2s = sf + 6208;
    const float* b4s = sf + 6220;

    uint32_t mb1 = sb + 8 + (uint32_t)(wg * 2) * 8;
    uint32_t mb2 = mb1 + 8;
    uint32_t base = sb + 26624 + (uint32_t)wg * 32768;
    uint32_t bE = base, bO = base + 16384;
    uint64_t dE = sdesc(bE), dO = sdesc(bO);
    uint64_t dW1h = sdesc(sb + 1024),  dW1l = sdesc(sb + 5120);
    uint64_t dW3h = sdesc(sb + 13312), dW3l = sdesc(sb + 17408);
    const uint32_t ID32 = (1u<<4) | (2u<<7) | (2u<<10) | (4u<<17) | (8u<<24);
    uint32_t tmw = tmem + (uint32_t)wg * 128;
    uint32_t ph1 = 0, ph2 = 0;
    int bid = wg + 1;
    uint32_t rE = bE + (uint32_t)wt * 128;
    uint32_t rO = bO + (uint32_t)wt * 128;
    int sx = wt & 7;
    const int STRIDE = 592;   // 148 blocks * 4 wg

    int s0 = blockIdx.x * 4 + wg;
    size_t gb = (size_t)(s0 >> 10) * CHW + (size_t)((s0 & 1023) << 8) + (size_t)(2 * wt);

    // prologue: load x(s0) -> X, issue stage1
    float fae[10], fao[10];
    {
        float xe[20], xo[20];
#pragma unroll
        for (int c = 0; c < 10; c++){
            float2 v = *reinterpret_cast<const float2*>(xh1 + gb + (size_t)c * HW);
            xe[c] = v.x; xo[c] = v.y;
        }
#pragma unroll
        for (int c = 0; c < 10; c++){
            float2 v = *reinterpret_cast<const float2*>(xh2 + gb + (size_t)c * HW);
            xe[10+c] = v.x; xo[10+c] = v.y;
        }
#pragma unroll
        for (int c = 0; c < 10; c++){
            float2 v = *reinterpret_cast<const float2*>(xf + gb + (size_t)c * HW);
            fae[c] = v.x; fao[c] = v.y;
        }
        store24(rE, sx, xe);
        store24(rO, sx, xo);
        fence_proxy();
        wg_bar(bid);
        if (wt == 0){
            tc_fence_after();
            issue_stage2t(tmw,      dE, dW1h, dW1l, ID32);
            issue_stage2t(tmw + 32, dO, dW1h, dW1l, ID32);
            tc_commit(mb1);
        }
    }

    for (int s = s0; s < NSUP; s += STRIDE){
        int sn = s + STRIDE;
        bool hasNext = sn < NSUP;
        int sl = hasNext ? sn : s;
        size_t gbn = (size_t)(sl >> 10) * CHW + (size_t)((sl & 1023) << 8) + (size_t)(2 * wt);

        // ---- epi1: conv2 for both pixels, msg out ----
        float msge[10], msgo[10];
        mbar_wait(mb1, ph1); ph1 ^= 1;
        tc_fence_after();
        {
            uint32_t de[32], dox[32];
            ldtm32(tmw, de); ldtm32(tmw + 32, dox);
            tc_wait_ld(); tc_fence_before();
            float he[32], ho[32];
#pragma unroll
            for (int j = 0; j < 32; j++){
                he[j] = fmaxf(__uint_as_float(de[j]), 0.f);
                ho[j] = fmaxf(__uint_as_float(dox[j]), 0.f);
            }
            conv2_pair(he, ho, w2s, b2s, msge, msgo);
        }
#pragma unroll
        for (int j = 0; j < 10; j++)
            *reinterpret_cast<float2*>(out + MSGOFF + gb + (size_t)j * HW) = make_float2(msge[j], msgo[j]);

        // ---- refill X := (xf, msg); issue stage2 ----
        {
            float ve[20], vo[20];
#pragma unroll
            for (int c = 0; c < 10; c++){
                ve[c] = fae[c]; ve[10+c] = msge[c];
                vo[c] = fao[c]; vo[10+c] = msgo[c];
            }
            store24(rE, sx, ve);
            store24(rO, sx, vo);
        }
        fence_proxy();
        wg_bar(bid);
        if (wt == 0){
            tc_fence_after();
            issue_stage2t(tmw + 64, dE, dW3h, dW3l, ID32);
            issue_stage2t(tmw + 96, dO, dW3h, dW3l, ID32);
            tc_commit(mb2);
        }

        // ---- prefetch next tile (overlaps stage2 MMA) ----
        float xne[20], xno[20], fne[10], fno[10];
#pragma unroll
        for (int c = 0; c < 10; c++){
            float2 v = *reinterpret_cast<const float2*>(xh1 + gbn + (size_t)c * HW);
            xne[c] = v.x; xno[c] = v.y;
        }
#pragma unroll
        for (int c = 0; c < 10; c++){
            float2 v = *reinterpret_cast<const float2*>(xh2 + gbn + (size_t)c * HW);
            xne[10+c] = v.x; xno[10+c] = v.y;
        }
#pragma unroll
        for (int c = 0; c < 10; c++){
            float2 v = *reinterpret_cast<const float2*>(xf + gbn + (size_t)c * HW);
            fne[c] = v.x; fno[c] = v.y;
        }

        // ---- wait stage2 done reading X, refill X := x(t+1), issue stage1(t+1) ----
        mbar_wait(mb2, ph2); ph2 ^= 1;
        tc_fence_after();
        store24(rE, sx, xne);
        store24(rO, sx, xno);
        fence_proxy();
        wg_bar(bid);
        if (wt == 0 && hasNext){
            tc_fence_after();
            issue_stage2t(tmw,      dE, dW1h, dW1l, ID32);
            issue_stage2t(tmw + 32, dO, dW1h, dW1l, ID32);
            tc_commit(mb1);
        }

        // ---- epi2: xf_new out (overlaps stage1(t+1) MMA) ----
        {
            uint32_t de[32], dox[32];
            ldtm32(tmw + 64, de); ldtm32(tmw + 96, dox);
            tc_wait_ld(); tc_fence_before();
            float he[32], ho[32];
#pragma unroll
            for (int j = 0; j < 32; j++){
                he[j] = fmaxf(__uint_as_float(de[j]), 0.f);
                ho[j] = fmaxf(__uint_as_float(dox[j]), 0.f);
            }
            float rese[10], reso[10];
            conv2_pair(he, ho, w4s, b4s, rese, reso);
#pragma unroll
            for (int j = 0; j < 10; j++)
                *reinterpret_cast<float2*>(out + gb + (size_t)j * HW) = make_float2(rese[j], reso[j]);
        }

        gb = gbn;
#pragma unroll
        for (int c = 0; c < 10; c++){ fae[c] = fne[c]; fao[c] = fno[c]; }
    }

    __syncthreads();
    if (tid < 32){
        asm volatile("tcgen05.dealloc.cta_group::1.sync.aligned.b32 %0, %1;" :: "r"(tmem), "r"(512u));
    }
#else
    // ------------------- fallback: round-2 ffma2 path -------------------
    extern __shared__ char smem[];
    float* sf = (float*)smem;
    {
        const float4* src = reinterpret_cast<const float4*>(g_fold + FBOFF);
        float4* dst = reinterpret_cast<float4*>(sf);
        for (int i = threadIdx.x; i < 534; i += 512) dst[i] = src[i];
    }
    __syncthreads();
    const float* sW1t = sf;
    const float* sW3t = sf + 640;
    const float* sW2f = sf + 1280;
    const float* sW4f = sf + 1664;
    const float* sB1  = sf + 2048;
    const float* sB3  = sf + 2080;
    const float* sB2  = sf + 2112;
    const float* sB4  = sf + 2124;

    const int stride = gridDim.x * 512;
    for (int t = blockIdx.x * 512 + threadIdx.x; t < 1048576; t += stride){
        int b  = t >> 17;
        int hw = (t & 0x1FFFF) << 1;
        size_t base = (size_t)b * CHW + hw;
        const float* ph1 = xh1 + base;
        const float* ph2 = xh2 + base;
        const float* pf  = xf  + base;
        float* po_new = out + base;
        float* po_msg = out + (size_t)MSGOFF + base;

        float2 xb[2][20];
#pragma unroll
        for (int c = 0; c < 10; c++) {
            float2 v = *reinterpret_cast<const float2*>(ph1 + (size_t)c * HW);
            xb[0][c] = make_float2(v.x, v.x);
            xb[1][c] = make_float2(v.y, v.y);
        }
#pragma unroll
        for (int c = 0; c < 10; c++) {
            float2 v = *reinterpret_cast<const float2*>(ph2 + (size_t)c * HW);
            xb[0][10 + c] = make_float2(v.x, v.x);
            xb[1][10 + c] = make_float2(v.y, v.y);
        }

        float2 msg2[5][2];
        run_block_fb(xb, sW1t, sB1, sW2f, sB2, msg2);

#pragma unroll
        for (int cp = 0; cp < 5; cp++) {
            float2 m0 = msg2[cp][0], m1 = msg2[cp][1];
            *reinterpret_cast<float2*>(po_msg + (size_t)(2 * cp)     * HW) = make_float2(m0.x, m1.x);
            *reinterpret_cast<float2*>(po_msg + (size_t)(2 * cp + 1) * HW) = make_float2(m0.y, m1.y);
            xb[0][10 + 2 * cp]     = make_float2(m0.x, m0.x);
            xb[0][10 + 2 * cp + 1] = make_float2(m0.y, m0.y);
            xb[1][10 + 2 * cp]     = make_float2(m1.x, m1.x);
            xb[1][10 + 2 * cp + 1] = make_float2(m1.y, m1.y);
        }
#pragma unroll
        for (int c = 0; c < 10; c++) {
            float2 v = *reinterpret_cast<const float2*>(pf + (size_t)c * HW);
            xb[0][c] = make_float2(v.x, v.x);
            xb[1][c] = make_float2(v.y, v.y);
        }

        float2 r2[5][2];
        run_block_fb(xb, sW3t, sB3, sW4f, sB4, r2);

#pragma unroll
        for (int cp = 0; cp < 5; cp++) {
            float2 r0 = r2[cp][0], r1 = r2[cp][1];
            *reinterpret_cast<float2*>(po_new + (size_t)(2 * cp)     * HW) = make_float2(r0.x, r1.x);
            *reinterpret_cast<float2*>(po_new + (size_t)(2 * cp + 1) * HW) = make_float2(r0.y, r1.y);
        }
    }
#endif
}

extern "C" void kernel_launch(void* const* d_in, const int* in_sizes, int n_in,
                              void* d_out, int out_size) {
    const float* xf  = (const float*)d_in[0];
    const float* xh1 = (const float*)d_in[1];
    const float* xh2 = (const float*)d_in[2];

    fold_kernel<<<1, 256>>>(
        (const float*)d_in[3],  (const float*)d_in[4],  (const float*)d_in[5],
        (const float*)d_in[6],  (const float*)d_in[7],
        (const float*)d_in[8],  (const float*)d_in[9],  (const float*)d_in[10],
        (const float*)d_in[11], (const float*)d_in[12],
        (const float*)d_in[13], (const float*)d_in[14], (const float*)d_in[15],
        (const float*)d_in[16], (const float*)d_in[17],
        (const float*)d_in[18], (const float*)d_in[19], (const float*)d_in[20],
        (const float*)d_in[21], (const float*)d_in[22]);

    cudaFuncSetAttribute(fused_kernel, cudaFuncAttributeMaxDynamicSharedMemorySize, 157696);
    fused_kernel<<<148, 512, 157696>>>(xf, xh1, xh2, (float*)d_out);
}